// round 11
// baseline (speedup 1.0000x reference)
#include <cuda_runtime.h>
#include <cuda_bf16.h>
#include <math.h>
#include <stdint.h>

// Problem dims
#define TT 16
#define BB 32
#define NN 512
#define FF 128
#define EE 2048            // F*T
#define K2 4096            // canonical split storage: [hi(2048) | lo(2048)]
#define NC 96              // K3=6144 virtual -> 96 chunks of 64 bf16
#define MROWS 16384        // B*N
#define ATT_ELEMS (32*512*512)
#define RES_ELEMS (16*512*128)

// ---------------- device scratch ----------------
__device__ float g_XR[(size_t)MROWS * EE];
__device__ float g_Att[(size_t)ATT_ELEMS];
__device__ float g_Abar[(size_t)512 * 512];
__device__ float g_OutBar[(size_t)512 * EE];
__device__ float g_w2[EE];
__device__ float g_vvec[MROWS];

// canonical split-bf16 buffers: row = [hi | lo], 4096 elems
__device__ __nv_bfloat16 g_XRs[(size_t)MROWS * K2];
__device__ __nv_bfloat16 g_Ys [(size_t)MROWS * K2];
__device__ __nv_bfloat16 g_M3s[(size_t)EE * K2];
__device__ __nv_bfloat16 g_WkTs[(size_t)EE * K2];
__device__ __nv_bfloat16 g_WqTs[(size_t)EE * K2];
__device__ __nv_bfloat16 g_Wvs [(size_t)EE * K2];
__device__ __nv_bfloat16 g_Wfcs[(size_t)EE * K2];
__device__ __nv_bfloat16 g_Zs  [(size_t)512 * K2];
__device__ __nv_bfloat16 g_Obars[(size_t)512 * K2];

// ================= helpers =================
__device__ __forceinline__ uint32_t smem_u32(const void* p) {
    uint32_t a;
    asm("{ .reg .u64 t; cvta.to.shared.u64 t, %1; cvt.u32.u64 %0, t; }" : "=r"(a) : "l"(p));
    return a;
}
#define SWZ128(off) ((off) ^ (((off) >> 3) & 0x70))

__device__ __forceinline__ void cp16(uint32_t s, const void* g) {
    asm volatile("cp.async.cg.shared.global [%0], [%1], 16;" :: "r"(s), "l"(g));
}
#define CP_COMMIT() asm volatile("cp.async.commit_group;" ::: "memory")
#define CP_WAIT1()  asm volatile("cp.async.wait_group 1;" ::: "memory")

__device__ __forceinline__ void ldmx4(uint32_t* f, uint32_t addr) {
    asm volatile("ldmatrix.sync.aligned.m8n8.x4.shared.b16 {%0,%1,%2,%3}, [%4];"
        : "=r"(f[0]), "=r"(f[1]), "=r"(f[2]), "=r"(f[3]) : "r"(addr));
}
__device__ __forceinline__ void mma16816(float* d, const uint32_t* a,
                                         uint32_t b0, uint32_t b1) {
    asm volatile("mma.sync.aligned.m16n8k16.row.col.f32.bf16.bf16.f32 "
        "{%0,%1,%2,%3}, {%4,%5,%6,%7}, {%8,%9}, {%0,%1,%2,%3};"
        : "+f"(d[0]), "+f"(d[1]), "+f"(d[2]), "+f"(d[3])
        : "r"(a[0]), "r"(a[1]), "r"(a[2]), "r"(a[3]), "r"(b0), "r"(b1));
}

// canonical split store: hi at p, lo at p+2048
__device__ __forceinline__ void store_split2(__nv_bfloat16* p, float x, float y) {
    __nv_bfloat162 h, l;
    h.x = __float2bfloat16(x); h.y = __float2bfloat16(y);
    l.x = __float2bfloat16(x - __bfloat162float(h.x));
    l.y = __float2bfloat16(y - __bfloat162float(h.y));
    *(__nv_bfloat162*)p = h;
    *(__nv_bfloat162*)(p + 2048) = l;
}

// chunk -> byte offset within canonical [hi|lo] row (8192 bytes)
// A operand pattern [H,L,H]; B operand pattern [H,H,L]
__device__ __forceinline__ int offA_of(int c) { return ((c < 64) ? c : c - 64) * 128; }
__device__ __forceinline__ int offB_of(int c) { return ((c < 32) ? c : c - 32) * 128; }

// 64x64 tile: per stage A 8KB + B 8KB
#define STAGE_BYTES 16384
#define NSTAGE 2
#define DSM_BYTES (NSTAGE * STAGE_BYTES + 128)

// ================= bf16 mma.sync NT GEMM, 64x64 tile, high occupancy ==============
// C = scale*(A3 @ B3^T) + bias; A3/B3 virtual K3=6144 split operands stored [R,4096].
// 64x64 tiles, 4 warps (warp tile 32x32), 96 chunks, 2-stage cp.async ring.
// emit: 0 -> fp32 C [Ncols, batched by sC]; 1 -> canonical split bf16 (ld=K2).
__global__ void __launch_bounds__(128, 6)
gemm_mma_nt(const __nv_bfloat16* __restrict__ A, const __nv_bfloat16* __restrict__ B,
            const float* __restrict__ bias, void* __restrict__ Cv,
            int Ncols, long long sA, long long sB, long long sC,
            float scale, int emit)
{
    extern __shared__ char sm[];
    A += (long long)blockIdx.z * sA;
    B += (long long)blockIdx.z * sB;

    const int tid = threadIdx.x, wid = tid >> 5, lane = tid & 31;
    const int row0 = blockIdx.y * 64, col0 = blockIdx.x * 64;
    const int wm = wid & 1, wn = wid >> 1;

    uint32_t sbase = (smem_u32(sm) + 127u) & ~127u;

    // loader: 128 threads, 2 per row (64 rows), 4x16B each for A and for B
    const int lrow = tid >> 1;
    const int lc0 = (tid & 1) * 4;
    const char* gA = (const char*)(A + (long long)(row0 + lrow) * K2);
    const char* gB = (const char*)(B + (long long)(col0 + lrow) * K2);
    uint32_t swo[4];
#pragma unroll
    for (int q = 0; q < 4; q++) {
        uint32_t off = (uint32_t)lrow * 128u + (lc0 + q) * 16u;
        swo[q] = SWZ128(off);
    }

    // prologue: chunks 0,1 -> stages 0,1
#pragma unroll
    for (int s = 0; s < 2; s++) {
        uint32_t aA = sbase + s * STAGE_BYTES;
        uint32_t aB = aA + 8192;
        int kb = s * 128;
#pragma unroll
        for (int q = 0; q < 4; q++) {
            cp16(aA + swo[q], gA + kb + (lc0 + q) * 16);
            cp16(aB + swo[q], gB + kb + (lc0 + q) * 16);
        }
        CP_COMMIT();
    }

    float acc[2][4][4];
#pragma unroll
    for (int mi = 0; mi < 2; mi++)
#pragma unroll
        for (int ni = 0; ni < 4; ni++)
#pragma unroll
            for (int r = 0; r < 4; r++) acc[mi][ni][r] = 0.f;

    const int fr = lane & 15;
    const int fk = (lane >> 4) * 16;
    uint32_t arow[2], brow[2];
#pragma unroll
    for (int mi = 0; mi < 2; mi++) arow[mi] = (uint32_t)(wm * 32 + mi * 16 + fr) * 128u;
#pragma unroll
    for (int bi = 0; bi < 2; bi++) brow[bi] = (uint32_t)(wn * 32 + bi * 16 + fr) * 128u;

    for (int c = 0; c < NC; c++) {
        CP_WAIT1();               // chunk c resident
        __syncthreads();          // visibility across threads

        uint32_t aA = sbase + (c & 1) * STAGE_BYTES;
        uint32_t aB = aA + 8192;
#pragma unroll
        for (int ks = 0; ks < 4; ks++) {
            const int kbyte = ks * 32 + fk;
            uint32_t af[2][4], bf[2][4];
            ldmx4(af[0], aA + SWZ128(arow[0] + kbyte));
            ldmx4(af[1], aA + SWZ128(arow[1] + kbyte));
            ldmx4(bf[0], aB + SWZ128(brow[0] + kbyte));
            ldmx4(bf[1], aB + SWZ128(brow[1] + kbyte));
#pragma unroll
            for (int mi = 0; mi < 2; mi++)
#pragma unroll
                for (int p = 0; p < 2; p++) {
                    mma16816(acc[mi][2 * p + 0], af[mi], bf[p][0], bf[p][2]);
                    mma16816(acc[mi][2 * p + 1], af[mi], bf[p][1], bf[p][3]);
                }
        }
        __syncthreads();          // all warps done with stage (c&1)

        if (c + 2 < NC) {
            int oA = offA_of(c + 2), oB = offB_of(c + 2);
#pragma unroll
            for (int q = 0; q < 4; q++) {
                cp16(aA + swo[q], gA + oA + (lc0 + q) * 16);
                cp16(aB + swo[q], gB + oB + (lc0 + q) * 16);
            }
        }
        CP_COMMIT();              // unconditional: keeps group numbering aligned
    }

    // epilogue
    if (emit == 0) {
        float* C = (float*)Cv + (long long)blockIdx.z * sC;
#pragma unroll
        for (int mi = 0; mi < 2; mi++) {
            int r = row0 + wm * 32 + mi * 16 + (lane >> 2);
#pragma unroll
            for (int ni = 0; ni < 4; ni++) {
                int cc = col0 + wn * 32 + ni * 8 + (lane & 3) * 2;
                float b0 = bias ? bias[cc] : 0.f;
                float b1 = bias ? bias[cc + 1] : 0.f;
                float2 v0, v1;
                v0.x = acc[mi][ni][0] * scale + b0;
                v0.y = acc[mi][ni][1] * scale + b1;
                v1.x = acc[mi][ni][2] * scale + b0;
                v1.y = acc[mi][ni][3] * scale + b1;
                *(float2*)(C + (long long)r * Ncols + cc) = v0;
                *(float2*)(C + (long long)(r + 8) * Ncols + cc) = v1;
            }
        }
    } else {
        __nv_bfloat16* C = (__nv_bfloat16*)Cv;
#pragma unroll
        for (int mi = 0; mi < 2; mi++) {
            int r = row0 + wm * 32 + mi * 16 + (lane >> 2);
#pragma unroll
            for (int ni = 0; ni < 4; ni++) {
                int cc = col0 + wn * 32 + ni * 8 + (lane & 3) * 2;
                float b0 = bias ? bias[cc] : 0.f;
                float b1 = bias ? bias[cc + 1] : 0.f;
                store_split2(C + (long long)r * K2 + cc,
                             acc[mi][ni][0] * scale + b0,
                             acc[mi][ni][1] * scale + b1);
                store_split2(C + (long long)(r + 8) * K2 + cc,
                             acc[mi][ni][2] * scale + b0,
                             acc[mi][ni][3] * scale + b1);
            }
        }
    }
}

// ================= elementwise kernels =================
__global__ void __launch_bounds__(256) split3(const float* __restrict__ X,
                                              __nv_bfloat16* __restrict__ Y, int n) {
    int i = blockIdx.x * 256 + threadIdx.x;
    if (i >= n) return;
    int r = i >> 11, k = i & 2047;
    float x = X[i];
    __nv_bfloat16 h = __float2bfloat16(x);
    __nv_bfloat16 l = __float2bfloat16(x - __bfloat162float(h));
    __nv_bfloat16* yr = Y + (size_t)r * K2;
    yr[k] = h;
    yr[2048 + k] = l;
}

__global__ void __launch_bounds__(256) split3t(const float* __restrict__ W,
                                               __nv_bfloat16* __restrict__ Y) {
    __shared__ float t[32][33];
    int tx = threadIdx.x & 31, ty = threadIdx.x >> 5;
    int cbase = blockIdx.x * 32;
    int rbase = blockIdx.y * 32;
#pragma unroll
    for (int j = 0; j < 4; j++)
        t[ty + j * 8][tx] = W[(size_t)(rbase + ty + j * 8) * EE + cbase + tx];
    __syncthreads();
#pragma unroll
    for (int j = 0; j < 4; j++) {
        int r = cbase + ty + j * 8;
        int k = rbase + tx;
        float x = t[tx][ty + j * 8];
        __nv_bfloat16 h = __float2bfloat16(x);
        __nv_bfloat16 l = __float2bfloat16(x - __bfloat162float(h));
        __nv_bfloat16* yr = Y + (size_t)r * K2;
        yr[k] = h;
        yr[2048 + k] = l;
    }
}

__global__ void __launch_bounds__(256) build_xr_split(const float* __restrict__ x,
                                                      float* __restrict__ xr,
                                                      __nv_bfloat16* __restrict__ xrs) {
    __shared__ float s[TT * 129];
    int bn = blockIdx.x;
    int b = bn >> 9, n = bn & 511;
    for (int i = threadIdx.x; i < TT * FF; i += 256) {
        int t = i >> 7, f = i & 127;
        s[t * 129 + f] = x[((size_t)(t * BB + b) * NN + n) * FF + f];
    }
    __syncthreads();
    for (int e = threadIdx.x; e < EE; e += 256) {
        int t = e & 15, f = e >> 4;
        float v = s[t * 129 + f];
        xr[(size_t)bn * EE + e] = v;
        __nv_bfloat16 h = __float2bfloat16(v);
        __nv_bfloat16 l = __float2bfloat16(v - __bfloat162float(h));
        size_t rb = (size_t)bn * K2 + e;
        xrs[rb] = h;
        xrs[rb + 2048] = l;
    }
}

__global__ void __launch_bounds__(256) wkbq_kernel(const float* __restrict__ Wk,
                                                   const float* __restrict__ bq,
                                                   float* __restrict__ w2) {
    int e = blockIdx.x * 256 + threadIdx.x;
    float s = 0.f;
    for (int d = 0; d < EE; d++) s += Wk[(size_t)d * EE + e] * bq[d];
    w2[e] = s;
}
__global__ void __launch_bounds__(256) xrw2_kernel(const float* __restrict__ XR,
                                                   const float* __restrict__ w2,
                                                   float* __restrict__ v, float scale) {
    int g = blockIdx.x * 8 + (threadIdx.x >> 5);
    int lane = threadIdx.x & 31;
    const float* r = XR + (size_t)g * EE;
    float s = 0.f;
    for (int e = lane; e < EE; e += 32) s += r[e] * w2[e];
#pragma unroll
    for (int o = 16; o; o >>= 1) s += __shfl_xor_sync(0xffffffffu, s, o);
    if (lane == 0) v[g] = s * scale;
}

__global__ void __launch_bounds__(128) softmax_rows(float* __restrict__ att,
                                                    const float* __restrict__ vadd) {
    size_t row = blockIdx.x;
    int b = (int)(row >> 9);
    float4* p = (float4*)(att + row * 512);
    const float4* vv = (const float4*)(vadd + (size_t)b * 512);
    float4 v = p[threadIdx.x];
    float4 a = vv[threadIdx.x];
    v.x += a.x; v.y += a.y; v.z += a.z; v.w += a.w;
    float m = fmaxf(fmaxf(v.x, v.y), fmaxf(v.z, v.w));
#pragma unroll
    for (int o = 16; o; o >>= 1) m = fmaxf(m, __shfl_xor_sync(0xffffffffu, m, o));
    __shared__ float sm[4];
    if ((threadIdx.x & 31) == 0) sm[threadIdx.x >> 5] = m;
    __syncthreads();
    m = fmaxf(fmaxf(sm[0], sm[1]), fmaxf(sm[2], sm[3]));
    v.x = __expf(v.x - m); v.y = __expf(v.y - m);
    v.z = __expf(v.z - m); v.w = __expf(v.w - m);
    float s = v.x + v.y + v.z + v.w;
#pragma unroll
    for (int o = 16; o; o >>= 1) s += __shfl_xor_sync(0xffffffffu, s, o);
    __shared__ float ss[4];
    if ((threadIdx.x & 31) == 0) ss[threadIdx.x >> 5] = s;
    __syncthreads();
    s = ss[0] + ss[1] + ss[2] + ss[3];
    float inv = 1.f / s;
    v.x *= inv; v.y *= inv; v.z *= inv; v.w *= inv;
    p[threadIdx.x] = v;
}

__global__ void __launch_bounds__(512) abar_kernel(const float* __restrict__ att,
                                                   float* __restrict__ abar) {
    int bg = blockIdx.x;
    int b = bg >> 4, g = bg & 15;
    const float* bse = att + ((size_t)b * 512 + g * 32) * 512;
    int j = threadIdx.x;
    float s = 0.f;
#pragma unroll 8
    for (int r = 0; r < 32; r++) s += bse[(size_t)r * 512 + j];
    abar[(size_t)bg * 512 + j] = s * (1.f / 32.f);
}

__global__ void __launch_bounds__(128) zbar_split(const float* __restrict__ abar,
                                                  const float* __restrict__ XR,
                                                  __nv_bfloat16* __restrict__ Zs) {
    int b = blockIdx.y;
    int col0 = blockIdx.x * 128;
    __shared__ float sA[16 * 512];
    for (int i = threadIdx.x; i < 16 * 512; i += 128)
        sA[i] = abar[(size_t)b * 16 * 512 + i];
    __syncthreads();
    float acc[16];
#pragma unroll
    for (int g = 0; g < 16; g++) acc[g] = 0.f;
    const float* vb = XR + (size_t)b * 512 * EE + col0 + threadIdx.x;
    for (int l = 0; l < 512; l++) {
        float vv = vb[(size_t)l * EE];
#pragma unroll
        for (int g = 0; g < 16; g++) acc[g] = fmaf(sA[g * 512 + l], vv, acc[g]);
    }
#pragma unroll
    for (int g = 0; g < 16; g++) {
        float v = acc[g];
        __nv_bfloat16 h = __float2bfloat16(v);
        __nv_bfloat16 l2 = __float2bfloat16(v - __bfloat162float(h));
        size_t rb = ((size_t)b * 16 + g) * K2 + col0 + threadIdx.x;
        Zs[rb] = h;
        Zs[rb + 2048] = l2;
    }
}

__global__ void __launch_bounds__(256) final_kernel(const float* __restrict__ x,
                                                    const float* __restrict__ outbar,
                                                    float* __restrict__ out) {
    int idx = blockIdx.x * 256 + threadIdx.x;
    int f = idx & 127;
    int i = (idx >> 7) & 511;
    int t = idx >> 16;
    const float* px = x + (size_t)t * (BB * NN * FF) + (size_t)i * FF + f;
    float s = 0.f;
#pragma unroll 8
    for (int b = 0; b < 32; b++) s += px[(size_t)b * (NN * FF)];
    out[idx] = s * (1.f / 32.f) + outbar[(size_t)i * EE + t * FF + f];
}

// ---------------- launcher ----------------
extern "C" void kernel_launch(void* const* d_in, const int* in_sizes, int n_in,
                              void* d_out, int out_size) {
    const float* x   = (const float*)d_in[0];
    const float* Wq  = (const float*)d_in[1];
    const float* bq  = (const float*)d_in[2];
    const float* Wk  = (const float*)d_in[3];
    const float* Wv  = (const float*)d_in[5];
    const float* bv  = (const float*)d_in[6];
    const float* Wfc = (const float*)d_in[7];
    const float* bfc = (const float*)d_in[8];
    float* out = (float*)d_out;

    float *pXR, *pAtt, *pAbar, *pOutBar, *pw2, *pv;
    __nv_bfloat16 *pXRs, *pYs, *pM3s, *pWkTs, *pWqTs, *pWvs, *pWfcs, *pZs, *pObars;
    cudaGetSymbolAddress((void**)&pXR, g_XR);
    cudaGetSymbolAddress((void**)&pAbar, g_Abar);
    cudaGetSymbolAddress((void**)&pOutBar, g_OutBar);
    cudaGetSymbolAddress((void**)&pw2, g_w2);
    cudaGetSymbolAddress((void**)&pv, g_vvec);
    cudaGetSymbolAddress((void**)&pXRs, g_XRs);
    cudaGetSymbolAddress((void**)&pYs, g_Ys);
    cudaGetSymbolAddress((void**)&pM3s, g_M3s);
    cudaGetSymbolAddress((void**)&pWkTs, g_WkTs);
    cudaGetSymbolAddress((void**)&pWqTs, g_WqTs);
    cudaGetSymbolAddress((void**)&pWvs, g_Wvs);
    cudaGetSymbolAddress((void**)&pWfcs, g_Wfcs);
    cudaGetSymbolAddress((void**)&pZs, g_Zs);
    cudaGetSymbolAddress((void**)&pObars, g_Obars);

    if (out_size >= RES_ELEMS + ATT_ELEMS) pAtt = out + RES_ELEMS;
    else cudaGetSymbolAddress((void**)&pAtt, g_Att);

    cudaFuncSetAttribute(gemm_mma_nt, cudaFuncAttributeMaxDynamicSharedMemorySize, DSM_BYTES);

    const float scale = rsqrtf((float)EE);
    const int nW = EE * EE;

    // 1) XR + canonical split (single pass over x)
    build_xr_split<<<MROWS, 256>>>(x, pXR, pXRs);

    // 2) M3 = Wk^T Wq  -> canonical split
    dim3 gT(64, 64);
    split3t<<<gT, 256>>>(Wk, pWkTs);
    split3t<<<gT, 256>>>(Wq, pWqTs);
    dim3 gM3(EE / 64, EE / 64);
    gemm_mma_nt<<<gM3, 128, DSM_BYTES>>>(pWkTs, pWqTs, nullptr, pM3s, 0, 0, 0, 0, 1.f, 1);

    // 3) Y = XR @ M3^T -> canonical split
    dim3 gY(EE / 64, MROWS / 64);
    gemm_mma_nt<<<gY, 128, DSM_BYTES>>>(pXRs, pM3s, nullptr, pYs, 0, 0, 0, 0, 1.f, 1);

    // 4) energy core = scale * Y_b XR_b^T  (batched over 32) -> fp32 att
    dim3 gE(512 / 64, 512 / 64, 32);
    gemm_mma_nt<<<gE, 128, DSM_BYTES>>>(pYs, pXRs, nullptr, pAtt, 512,
                                        (long long)512 * K2, (long long)512 * K2,
                                        (long long)512 * 512, scale, 0);

    // 5) bias column vector; softmax with +v[j]
    wkbq_kernel<<<EE / 256, 256>>>(Wk, bq, pw2);
    xrw2_kernel<<<MROWS / 8, 256>>>(pXR, pw2, pv, scale);
    softmax_rows<<<32 * 512, 128>>>(pAtt, pv);

    // 6) Abar, Z = Abar @ XR (canonical split emitted)
    abar_kernel<<<512, 512>>>(pAtt, pAbar);
    dim3 gZ(EE / 128, 32);
    zbar_split<<<gZ, 128>>>(pAbar, pXR, pZs);

    // 7) Obar = Z @ Wv^T + bv -> canonical split
    split3<<<(nW + 255) / 256, 256>>>(Wv, pWvs, nW);
    dim3 gOb(EE / 64, 512 / 64);
    gemm_mma_nt<<<gOb, 128, DSM_BYTES>>>(pZs, pWvs, bv, pObars, 0, 0, 0, 0, 1.f, 1);

    // 8) OutBar = Obar @ Wfc^T + bfc -> fp32
    split3<<<(nW + 255) / 256, 256>>>(Wfc, pWfcs, nW);
    gemm_mma_nt<<<gOb, 128, DSM_BYTES>>>(pObars, pWfcs, bfc, pOutBar, EE, 0, 0, 0, 1.f, 0);

    // 9) final output
    final_kernel<<<RES_ELEMS / 256, 256>>>(x, pOutBar, out);
}

// round 12
// speedup vs baseline: 1.0083x; 1.0083x over previous
#include <cuda_runtime.h>
#include <cuda_bf16.h>
#include <math.h>
#include <stdint.h>

// Problem dims
#define TT 16
#define BB 32
#define NN 512
#define FF 128
#define EE 2048            // F*T
#define K2 4096            // canonical split storage: [hi(2048) | lo(2048)]
#define NC 96              // K3=6144 virtual -> 96 chunks of 64 bf16
#define NSUPER 48          // 48 super-chunks of 128 bf16 (2 virtual chunks each)
#define MROWS 16384        // B*N
#define ATT_ELEMS (32*512*512)
#define RES_ELEMS (16*512*128)

// ---------------- device scratch ----------------
__device__ float g_XR[(size_t)MROWS * EE];
__device__ float g_Att[(size_t)ATT_ELEMS];
__device__ float g_Abar[(size_t)512 * 512];
__device__ float g_OutBar[(size_t)512 * EE];
__device__ float g_w2[EE];
__device__ float g_vvec[MROWS];

// canonical split-bf16 buffers: row = [hi | lo], 4096 elems
__device__ __nv_bfloat16 g_XRs[(size_t)MROWS * K2];
__device__ __nv_bfloat16 g_Ys [(size_t)MROWS * K2];
__device__ __nv_bfloat16 g_M3s[(size_t)EE * K2];
__device__ __nv_bfloat16 g_WkTs[(size_t)EE * K2];
__device__ __nv_bfloat16 g_WqTs[(size_t)EE * K2];
__device__ __nv_bfloat16 g_Wvs [(size_t)EE * K2];
__device__ __nv_bfloat16 g_Wfcs[(size_t)EE * K2];
__device__ __nv_bfloat16 g_Zs  [(size_t)512 * K2];
__device__ __nv_bfloat16 g_Obars[(size_t)512 * K2];

// ================= helpers =================
__device__ __forceinline__ uint32_t smem_u32(const void* p) {
    uint32_t a;
    asm("{ .reg .u64 t; cvta.to.shared.u64 t, %1; cvt.u32.u64 %0, t; }" : "=r"(a) : "l"(p));
    return a;
}
#define SWZ128(off) ((off) ^ (((off) >> 3) & 0x70))

__device__ __forceinline__ void cp16(uint32_t s, const void* g) {
    asm volatile("cp.async.cg.shared.global [%0], [%1], 16;" :: "r"(s), "l"(g));
}
#define CP_COMMIT() asm volatile("cp.async.commit_group;" ::: "memory")
#define CP_WAIT0()  asm volatile("cp.async.wait_group 0;" ::: "memory")

__device__ __forceinline__ void ldmx4(uint32_t* f, uint32_t addr) {
    asm volatile("ldmatrix.sync.aligned.m8n8.x4.shared.b16 {%0,%1,%2,%3}, [%4];"
        : "=r"(f[0]), "=r"(f[1]), "=r"(f[2]), "=r"(f[3]) : "r"(addr));
}
__device__ __forceinline__ void mma16816(float* d, const uint32_t* a,
                                         uint32_t b0, uint32_t b1) {
    asm volatile("mma.sync.aligned.m16n8k16.row.col.f32.bf16.bf16.f32 "
        "{%0,%1,%2,%3}, {%4,%5,%6,%7}, {%8,%9}, {%0,%1,%2,%3};"
        : "+f"(d[0]), "+f"(d[1]), "+f"(d[2]), "+f"(d[3])
        : "r"(a[0]), "r"(a[1]), "r"(a[2]), "r"(a[3]), "r"(b0), "r"(b1));
}

// canonical split store: hi at p, lo at p+2048
__device__ __forceinline__ void store_split2(__nv_bfloat16* p, float x, float y) {
    __nv_bfloat162 h, l;
    h.x = __float2bfloat16(x); h.y = __float2bfloat16(y);
    l.x = __float2bfloat16(x - __bfloat162float(h.x));
    l.y = __float2bfloat16(y - __bfloat162float(h.y));
    *(__nv_bfloat162*)p = h;
    *(__nv_bfloat162*)(p + 2048) = l;
}

// virtual chunk -> byte offset within canonical [hi|lo] row (8192 bytes)
// A operand pattern [H,L,H]; B operand pattern [H,H,L]
__device__ __forceinline__ int offA_of(int c) { return ((c < 64) ? c : c - 64) * 128; }
__device__ __forceinline__ int offB_of(int c) { return ((c < 32) ? c : c - 32) * 128; }

// super-stage: A(2x16KB) + B(2x16KB) = 64KB; two stages = 128KB
#define SUPER_BYTES 65536
#define DSM_BYTES (2 * SUPER_BYTES + 128)

// ================= bf16 mma.sync NT GEMM, 128x128 tile, BK=128, 1 CTA/SM =========
// C = scale*(A3 @ B3^T) + bias; A3/B3 virtual K3=6144 split operands stored [R,4096].
// 48 super-chunks of 128 bf16; 2-super-stage pipeline, ONE barrier per super-chunk.
// emit: 0 -> fp32 C [Ncols, batched by sC]; 1 -> canonical split bf16 (ld=K2).
__global__ void __launch_bounds__(256, 1)
gemm_mma_nt(const __nv_bfloat16* __restrict__ A, const __nv_bfloat16* __restrict__ B,
            const float* __restrict__ bias, void* __restrict__ Cv,
            int Ncols, long long sA, long long sB, long long sC,
            float scale, int emit)
{
    extern __shared__ char sm[];
    A += (long long)blockIdx.z * sA;
    B += (long long)blockIdx.z * sB;

    const int tid = threadIdx.x, wid = tid >> 5, lane = tid & 31;
    const int row0 = blockIdx.y * 128, col0 = blockIdx.x * 128;
    const int wm = wid & 3, wn = wid >> 2;

    uint32_t sbase = (smem_u32(sm) + 127u) & ~127u;

    // loader: per 16KB sub-block, 2 threads per row (128 rows), 4 x 16B each
    const int lrow = tid >> 1;
    const int lc0 = (tid & 1) * 4;
    const char* gA = (const char*)(A + (long long)(row0 + lrow) * K2);
    const char* gB = (const char*)(B + (long long)(col0 + lrow) * K2);
    uint32_t swo[4];
#pragma unroll
    for (int q = 0; q < 4; q++) {
        uint32_t off = (uint32_t)lrow * 128u + (lc0 + q) * 16u;
        swo[q] = SWZ128(off);
    }

    // prefetch of super-chunk p into stage st: A sub-blocks at +j*16K, B at +32K+j*16K
    auto prefetch_super = [&](int p, uint32_t stageBase) {
#pragma unroll
        for (int j = 0; j < 2; j++) {
            int vc = 2 * p + j;
            int oA = offA_of(vc), oB = offB_of(vc);
            uint32_t dA = stageBase + j * 16384;
            uint32_t dB = stageBase + 32768 + j * 16384;
#pragma unroll
            for (int q = 0; q < 4; q++) {
                cp16(dA + swo[q], gA + oA + (lc0 + q) * 16);
                cp16(dB + swo[q], gB + oB + (lc0 + q) * 16);
            }
        }
        CP_COMMIT();
    };

    // prologue: super 0 -> stage 0
    prefetch_super(0, sbase);

    float acc[2][8][4];
#pragma unroll
    for (int mi = 0; mi < 2; mi++)
#pragma unroll
        for (int ni = 0; ni < 8; ni++)
#pragma unroll
            for (int r = 0; r < 4; r++) acc[mi][ni][r] = 0.f;

    const int fr = lane & 15;
    const int fk = (lane >> 4) * 16;
    uint32_t arow[2], brow[4];
#pragma unroll
    for (int mi = 0; mi < 2; mi++) arow[mi] = (uint32_t)(wm * 32 + mi * 16 + fr) * 128u;
#pragma unroll
    for (int bi = 0; bi < 4; bi++) brow[bi] = (uint32_t)(wn * 64 + bi * 16 + fr) * 128u;

    for (int p = 0; p < NSUPER; p++) {
        CP_WAIT0();               // super p resident (own thread's issues)
        __syncthreads();          // all threads: p resident; all done computing p-1

        // prefetch super p+1 into the other stage (free: p-1 consumed by all)
        if (p + 1 < NSUPER)
            prefetch_super(p + 1, sbase + ((p + 1) & 1) * SUPER_BYTES);

        // compute super p: 2 sub-chunks x 4 k-steps x 16 MMAs, no barriers inside
        uint32_t stage = sbase + (p & 1) * SUPER_BYTES;
#pragma unroll
        for (int j = 0; j < 2; j++) {
            uint32_t aA = stage + j * 16384;
            uint32_t aB = stage + 32768 + j * 16384;
#pragma unroll
            for (int ks = 0; ks < 4; ks++) {
                const int kbyte = ks * 32 + fk;
                uint32_t af[2][4], bf[4][4];
                ldmx4(af[0], aA + SWZ128(arow[0] + kbyte));
                ldmx4(af[1], aA + SWZ128(arow[1] + kbyte));
                ldmx4(bf[0], aB + SWZ128(brow[0] + kbyte));
                ldmx4(bf[1], aB + SWZ128(brow[1] + kbyte));
                ldmx4(bf[2], aB + SWZ128(brow[2] + kbyte));
                ldmx4(bf[3], aB + SWZ128(brow[3] + kbyte));
#pragma unroll
                for (int bi = 0; bi < 4; bi++)
#pragma unroll
                    for (int mi = 0; mi < 2; mi++) {
                        mma16816(acc[mi][2 * bi + 0], af[mi], bf[bi][0], bf[bi][2]);
                        mma16816(acc[mi][2 * bi + 1], af[mi], bf[bi][1], bf[bi][3]);
                    }
            }
        }
    }

    // epilogue
    if (emit == 0) {
        float* C = (float*)Cv + (long long)blockIdx.z * sC;
#pragma unroll
        for (int mi = 0; mi < 2; mi++) {
            int r = row0 + wm * 32 + mi * 16 + (lane >> 2);
#pragma unroll
            for (int ni = 0; ni < 8; ni++) {
                int cc = col0 + wn * 64 + ni * 8 + (lane & 3) * 2;
                float b0 = bias ? bias[cc] : 0.f;
                float b1 = bias ? bias[cc + 1] : 0.f;
                float2 v0, v1;
                v0.x = acc[mi][ni][0] * scale + b0;
                v0.y = acc[mi][ni][1] * scale + b1;
                v1.x = acc[mi][ni][2] * scale + b0;
                v1.y = acc[mi][ni][3] * scale + b1;
                *(float2*)(C + (long long)r * Ncols + cc) = v0;
                *(float2*)(C + (long long)(r + 8) * Ncols + cc) = v1;
            }
        }
    } else {
        __nv_bfloat16* C = (__nv_bfloat16*)Cv;
#pragma unroll
        for (int mi = 0; mi < 2; mi++) {
            int r = row0 + wm * 32 + mi * 16 + (lane >> 2);
#pragma unroll
            for (int ni = 0; ni < 8; ni++) {
                int cc = col0 + wn * 64 + ni * 8 + (lane & 3) * 2;
                float b0 = bias ? bias[cc] : 0.f;
                float b1 = bias ? bias[cc + 1] : 0.f;
                store_split2(C + (long long)r * K2 + cc,
                             acc[mi][ni][0] * scale + b0,
                             acc[mi][ni][1] * scale + b1);
                store_split2(C + (long long)(r + 8) * K2 + cc,
                             acc[mi][ni][2] * scale + b0,
                             acc[mi][ni][3] * scale + b1);
            }
        }
    }
}

// ================= elementwise kernels =================
__global__ void __launch_bounds__(256) split3(const float* __restrict__ X,
                                              __nv_bfloat16* __restrict__ Y, int n) {
    int i = blockIdx.x * 256 + threadIdx.x;
    if (i >= n) return;
    int r = i >> 11, k = i & 2047;
    float x = X[i];
    __nv_bfloat16 h = __float2bfloat16(x);
    __nv_bfloat16 l = __float2bfloat16(x - __bfloat162float(h));
    __nv_bfloat16* yr = Y + (size_t)r * K2;
    yr[k] = h;
    yr[2048 + k] = l;
}

__global__ void __launch_bounds__(256) split3t(const float* __restrict__ W,
                                               __nv_bfloat16* __restrict__ Y) {
    __shared__ float t[32][33];
    int tx = threadIdx.x & 31, ty = threadIdx.x >> 5;
    int cbase = blockIdx.x * 32;
    int rbase = blockIdx.y * 32;
#pragma unroll
    for (int j = 0; j < 4; j++)
        t[ty + j * 8][tx] = W[(size_t)(rbase + ty + j * 8) * EE + cbase + tx];
    __syncthreads();
#pragma unroll
    for (int j = 0; j < 4; j++) {
        int r = cbase + ty + j * 8;
        int k = rbase + tx;
        float x = t[tx][ty + j * 8];
        __nv_bfloat16 h = __float2bfloat16(x);
        __nv_bfloat16 l = __float2bfloat16(x - __bfloat162float(h));
        __nv_bfloat16* yr = Y + (size_t)r * K2;
        yr[k] = h;
        yr[2048 + k] = l;
    }
}

__global__ void __launch_bounds__(256) build_xr_split(const float* __restrict__ x,
                                                      float* __restrict__ xr,
                                                      __nv_bfloat16* __restrict__ xrs) {
    __shared__ float s[TT * 129];
    int bn = blockIdx.x;
    int b = bn >> 9, n = bn & 511;
    for (int i = threadIdx.x; i < TT * FF; i += 256) {
        int t = i >> 7, f = i & 127;
        s[t * 129 + f] = x[((size_t)(t * BB + b) * NN + n) * FF + f];
    }
    __syncthreads();
    for (int e = threadIdx.x; e < EE; e += 256) {
        int t = e & 15, f = e >> 4;
        float v = s[t * 129 + f];
        xr[(size_t)bn * EE + e] = v;
        __nv_bfloat16 h = __float2bfloat16(v);
        __nv_bfloat16 l = __float2bfloat16(v - __bfloat162float(h));
        size_t rb = (size_t)bn * K2 + e;
        xrs[rb] = h;
        xrs[rb + 2048] = l;
    }
}

__global__ void __launch_bounds__(256) wkbq_kernel(const float* __restrict__ Wk,
                                                   const float* __restrict__ bq,
                                                   float* __restrict__ w2) {
    int e = blockIdx.x * 256 + threadIdx.x;
    float s = 0.f;
    for (int d = 0; d < EE; d++) s += Wk[(size_t)d * EE + e] * bq[d];
    w2[e] = s;
}
__global__ void __launch_bounds__(256) xrw2_kernel(const float* __restrict__ XR,
                                                   const float* __restrict__ w2,
                                                   float* __restrict__ v, float scale) {
    int g = blockIdx.x * 8 + (threadIdx.x >> 5);
    int lane = threadIdx.x & 31;
    const float* r = XR + (size_t)g * EE;
    float s = 0.f;
    for (int e = lane; e < EE; e += 32) s += r[e] * w2[e];
#pragma unroll
    for (int o = 16; o; o >>= 1) s += __shfl_xor_sync(0xffffffffu, s, o);
    if (lane == 0) v[g] = s * scale;
}

__global__ void __launch_bounds__(128) softmax_rows(float* __restrict__ att,
                                                    const float* __restrict__ vadd) {
    size_t row = blockIdx.x;
    int b = (int)(row >> 9);
    float4* p = (float4*)(att + row * 512);
    const float4* vv = (const float4*)(vadd + (size_t)b * 512);
    float4 v = p[threadIdx.x];
    float4 a = vv[threadIdx.x];
    v.x += a.x; v.y += a.y; v.z += a.z; v.w += a.w;
    float m = fmaxf(fmaxf(v.x, v.y), fmaxf(v.z, v.w));
#pragma unroll
    for (int o = 16; o; o >>= 1) m = fmaxf(m, __shfl_xor_sync(0xffffffffu, m, o));
    __shared__ float sm[4];
    if ((threadIdx.x & 31) == 0) sm[threadIdx.x >> 5] = m;
    __syncthreads();
    m = fmaxf(fmaxf(sm[0], sm[1]), fmaxf(sm[2], sm[3]));
    v.x = __expf(v.x - m); v.y = __expf(v.y - m);
    v.z = __expf(v.z - m); v.w = __expf(v.w - m);
    float s = v.x + v.y + v.z + v.w;
#pragma unroll
    for (int o = 16; o; o >>= 1) s += __shfl_xor_sync(0xffffffffu, s, o);
    __shared__ float ss[4];
    if ((threadIdx.x & 31) == 0) ss[threadIdx.x >> 5] = s;
    __syncthreads();
    s = ss[0] + ss[1] + ss[2] + ss[3];
    float inv = 1.f / s;
    v.x *= inv; v.y *= inv; v.z *= inv; v.w *= inv;
    p[threadIdx.x] = v;
}

__global__ void __launch_bounds__(512) abar_kernel(const float* __restrict__ att,
                                                   float* __restrict__ abar) {
    int bg = blockIdx.x;
    int b = bg >> 4, g = bg & 15;
    const float* bse = att + ((size_t)b * 512 + g * 32) * 512;
    int j = threadIdx.x;
    float s = 0.f;
#pragma unroll 8
    for (int r = 0; r < 32; r++) s += bse[(size_t)r * 512 + j];
    abar[(size_t)bg * 512 + j] = s * (1.f / 32.f);
}

__global__ void __launch_bounds__(128) zbar_split(const float* __restrict__ abar,
                                                  const float* __restrict__ XR,
                                                  __nv_bfloat16* __restrict__ Zs) {
    int b = blockIdx.y;
    int col0 = blockIdx.x * 128;
    __shared__ float sA[16 * 512];
    for (int i = threadIdx.x; i < 16 * 512; i += 128)
        sA[i] = abar[(size_t)b * 16 * 512 + i];
    __syncthreads();
    float acc[16];
#pragma unroll
    for (int g = 0; g < 16; g++) acc[g] = 0.f;
    const float* vb = XR + (size_t)b * 512 * EE + col0 + threadIdx.x;
    for (int l = 0; l < 512; l++) {
        float vv = vb[(size_t)l * EE];
#pragma unroll
        for (int g = 0; g < 16; g++) acc[g] = fmaf(sA[g * 512 + l], vv, acc[g]);
    }
#pragma unroll
    for (int g = 0; g < 16; g++) {
        float v = acc[g];
        __nv_bfloat16 h = __float2bfloat16(v);
        __nv_bfloat16 l2 = __float2bfloat16(v - __bfloat162float(h));
        size_t rb = ((size_t)b * 16 + g) * K2 + col0 + threadIdx.x;
        Zs[rb] = h;
        Zs[rb + 2048] = l2;
    }
}

__global__ void __launch_bounds__(256) final_kernel(const float* __restrict__ x,
                                                    const float* __restrict__ outbar,
                                                    float* __restrict__ out) {
    int idx = blockIdx.x * 256 + threadIdx.x;
    int f = idx & 127;
    int i = (idx >> 7) & 511;
    int t = idx >> 16;
    const float* px = x + (size_t)t * (BB * NN * FF) + (size_t)i * FF + f;
    float s = 0.f;
#pragma unroll 8
    for (int b = 0; b < 32; b++) s += px[(size_t)b * (NN * FF)];
    out[idx] = s * (1.f / 32.f) + outbar[(size_t)i * EE + t * FF + f];
}

// ---------------- launcher ----------------
extern "C" void kernel_launch(void* const* d_in, const int* in_sizes, int n_in,
                              void* d_out, int out_size) {
    const float* x   = (const float*)d_in[0];
    const float* Wq  = (const float*)d_in[1];
    const float* bq  = (const float*)d_in[2];
    const float* Wk  = (const float*)d_in[3];
    const float* Wv  = (const float*)d_in[5];
    const float* bv  = (const float*)d_in[6];
    const float* Wfc = (const float*)d_in[7];
    const float* bfc = (const float*)d_in[8];
    float* out = (float*)d_out;

    float *pXR, *pAtt, *pAbar, *pOutBar, *pw2, *pv;
    __nv_bfloat16 *pXRs, *pYs, *pM3s, *pWkTs, *pWqTs, *pWvs, *pWfcs, *pZs, *pObars;
    cudaGetSymbolAddress((void**)&pXR, g_XR);
    cudaGetSymbolAddress((void**)&pAbar, g_Abar);
    cudaGetSymbolAddress((void**)&pOutBar, g_OutBar);
    cudaGetSymbolAddress((void**)&pw2, g_w2);
    cudaGetSymbolAddress((void**)&pv, g_vvec);
    cudaGetSymbolAddress((void**)&pXRs, g_XRs);
    cudaGetSymbolAddress((void**)&pYs, g_Ys);
    cudaGetSymbolAddress((void**)&pM3s, g_M3s);
    cudaGetSymbolAddress((void**)&pWkTs, g_WkTs);
    cudaGetSymbolAddress((void**)&pWqTs, g_WqTs);
    cudaGetSymbolAddress((void**)&pWvs, g_Wvs);
    cudaGetSymbolAddress((void**)&pWfcs, g_Wfcs);
    cudaGetSymbolAddress((void**)&pZs, g_Zs);
    cudaGetSymbolAddress((void**)&pObars, g_Obars);

    if (out_size >= RES_ELEMS + ATT_ELEMS) pAtt = out + RES_ELEMS;
    else cudaGetSymbolAddress((void**)&pAtt, g_Att);

    cudaFuncSetAttribute(gemm_mma_nt, cudaFuncAttributeMaxDynamicSharedMemorySize, DSM_BYTES);

    const float scale = rsqrtf((float)EE);
    const int nW = EE * EE;

    // 1) XR + canonical split (single pass over x)
    build_xr_split<<<MROWS, 256>>>(x, pXR, pXRs);

    // 2) M3 = Wk^T Wq  -> canonical split
    dim3 gT(64, 64);
    split3t<<<gT, 256>>>(Wk, pWkTs);
    split3t<<<gT, 256>>>(Wq, pWqTs);
    dim3 gM3(EE / 128, EE / 128);
    gemm_mma_nt<<<gM3, 256, DSM_BYTES>>>(pWkTs, pWqTs, nullptr, pM3s, 0, 0, 0, 0, 1.f, 1);

    // 3) Y = XR @ M3^T -> canonical split
    dim3 gY(EE / 128, MROWS / 128);
    gemm_mma_nt<<<gY, 256, DSM_BYTES>>>(pXRs, pM3s, nullptr, pYs, 0, 0, 0, 0, 1.f, 1);

    // 4) energy core = scale * Y_b XR_b^T  (batched over 32) -> fp32 att
    dim3 gE(512 / 128, 512 / 128, 32);
    gemm_mma_nt<<<gE, 256, DSM_BYTES>>>(pYs, pXRs, nullptr, pAtt, 512,
                                        (long long)512 * K2, (long long)512 * K2,
                                        (long long)512 * 512, scale, 0);

    // 5) bias column vector; softmax with +v[j]
    wkbq_kernel<<<EE / 256, 256>>>(Wk, bq, pw2);
    xrw2_kernel<<<MROWS / 8, 256>>>(pXR, pw2, pv, scale);
    softmax_rows<<<32 * 512, 128>>>(pAtt, pv);

    // 6) Abar, Z = Abar @ XR (canonical split emitted)
    abar_kernel<<<512, 512>>>(pAtt, pAbar);
    dim3 gZ(EE / 128, 32);
    zbar_split<<<gZ, 128>>>(pAbar, pXR, pZs);

    // 7) Obar = Z @ Wv^T + bv -> canonical split
    split3<<<(nW + 255) / 256, 256>>>(Wv, pWvs, nW);
    dim3 gOb(EE / 128, 512 / 128);
    gemm_mma_nt<<<gOb, 256, DSM_BYTES>>>(pZs, pWvs, bv, pObars, 0, 0, 0, 0, 1.f, 1);

    // 8) OutBar = Obar @ Wfc^T + bfc -> fp32
    split3<<<(nW + 255) / 256, 256>>>(Wfc, pWfcs, nW);
    gemm_mma_nt<<<gOb, 256, DSM_BYTES>>>(pObars, pWfcs, bfc, pOutBar, EE, 0, 0, 0, 1.f, 0);

    // 9) final output
    final_kernel<<<RES_ELEMS / 256, 256>>>(x, pOutBar, out);
}

// round 13
// speedup vs baseline: 1.4764x; 1.4642x over previous
#include <cuda_runtime.h>
#include <cuda_bf16.h>
#include <cuda_fp16.h>
#include <math.h>
#include <stdint.h>

// Problem dims
#define TT 16
#define BB 32
#define NN 512
#define FF 128
#define EE 2048            // F*T
#define K2 4096            // canonical split row length (hi|lo), bf16 or fp16
#define MROWS 16384        // B*N
#define ATT_ELEMS (32*512*512)
#define RES_ELEMS (16*512*128)

// ---------------- device scratch ----------------
__device__ float g_XR[(size_t)MROWS * EE];
__device__ float g_Att[(size_t)ATT_ELEMS];
__device__ float g_Abar[(size_t)512 * 512];
__device__ float g_OutBar[(size_t)512 * EE];
__device__ float g_w2[EE];
__device__ float g_vvec[MROWS];

// fp16 split buffers (rows = [hi(2048) | lo(2048)])
__device__ __half g_XR16[(size_t)MROWS * K2];
__device__ __half g_Y16 [(size_t)MROWS * K2];
__device__ __half g_WkT16[(size_t)EE * K2];
__device__ __half g_WqT16[(size_t)EE * K2];
__device__ __half g_M3h[(size_t)EE * EE];          // fp16 single
// bf16 canonical split buffers (result path)
__device__ __nv_bfloat16 g_Wvs [(size_t)EE * K2];
__device__ __nv_bfloat16 g_Wfcs[(size_t)EE * K2];
__device__ __nv_bfloat16 g_Zs  [(size_t)512 * K2];
__device__ __nv_bfloat16 g_Obars[(size_t)512 * K2];

// ================= helpers =================
__device__ __forceinline__ uint32_t smem_u32(const void* p) {
    uint32_t a;
    asm("{ .reg .u64 t; cvta.to.shared.u64 t, %1; cvt.u32.u64 %0, t; }" : "=r"(a) : "l"(p));
    return a;
}
#define SWZ128(off) ((off) ^ (((off) >> 3) & 0x70))

__device__ __forceinline__ void cp16(uint32_t s, const void* g) {
    asm volatile("cp.async.cg.shared.global [%0], [%1], 16;" :: "r"(s), "l"(g));
}
#define CP_COMMIT() asm volatile("cp.async.commit_group;" ::: "memory")
#define CP_WAIT1()  asm volatile("cp.async.wait_group 1;" ::: "memory")

__device__ __forceinline__ void ldmx4(uint32_t* f, uint32_t addr) {
    asm volatile("ldmatrix.sync.aligned.m8n8.x4.shared.b16 {%0,%1,%2,%3}, [%4];"
        : "=r"(f[0]), "=r"(f[1]), "=r"(f[2]), "=r"(f[3]) : "r"(addr));
}
template <bool FP16>
__device__ __forceinline__ void mma16816(float* d, const uint32_t* a,
                                         uint32_t b0, uint32_t b1) {
    if constexpr (FP16) {
        asm volatile("mma.sync.aligned.m16n8k16.row.col.f32.f16.f16.f32 "
            "{%0,%1,%2,%3}, {%4,%5,%6,%7}, {%8,%9}, {%0,%1,%2,%3};"
            : "+f"(d[0]), "+f"(d[1]), "+f"(d[2]), "+f"(d[3])
            : "r"(a[0]), "r"(a[1]), "r"(a[2]), "r"(a[3]), "r"(b0), "r"(b1));
    } else {
        asm volatile("mma.sync.aligned.m16n8k16.row.col.f32.bf16.bf16.f32 "
            "{%0,%1,%2,%3}, {%4,%5,%6,%7}, {%8,%9}, {%0,%1,%2,%3};"
            : "+f"(d[0]), "+f"(d[1]), "+f"(d[2]), "+f"(d[3])
            : "r"(a[0]), "r"(a[1]), "r"(a[2]), "r"(a[3]), "r"(b0), "r"(b1));
    }
}

__device__ __forceinline__ void store_split2_bf16(__nv_bfloat16* p, float x, float y) {
    __nv_bfloat162 h, l;
    h.x = __float2bfloat16(x); h.y = __float2bfloat16(y);
    l.x = __float2bfloat16(x - __bfloat162float(h.x));
    l.y = __float2bfloat16(y - __bfloat162float(h.y));
    *(__nv_bfloat162*)p = h;
    *(__nv_bfloat162*)(p + 2048) = l;
}
__device__ __forceinline__ void store_split2_f16(__half* p, float x, float y) {
    __half2 h, l;
    h.x = __float2half(x); h.y = __float2half(y);
    l.x = __float2half(x - __half2float(h.x));
    l.y = __float2half(y - __half2float(h.y));
    *(__half2*)p = h;
    *(__half2*)(p + 2048) = l;
}

#define STAGE_BYTES 32768      // A 16KB + B 16KB (128 rows x 128B per chunk)
#define DSM_BYTES (3 * STAGE_BYTES + 128)

// ================= templated mma.sync NT GEMM ==================================
// Virtual K = NCc chunks of 64 elems (128B). Chunk c reads A row offset
// (c<TA ? c : c-TA)*128 bytes, B row offset (c<TB ? c : c-TB)*128.
//   bf16 3-term: NCc=96, TA=64, TB=32 over canonical [hi|lo] (8KB rows)
//   fp16 2-term: NCc=64, TA=64 (full [hi|lo]), TB=32 (hi only; ldB may be 4KB)
// emit: 0 fp32 C (ld Ncols, batch sC elems); 1 bf16 canonical split (ld 4096);
//       2 fp16 single (ld 2048); 3 fp16 canonical split (ld 4096)
template <bool FP16>
__global__ void __launch_bounds__(256, 2)
gemm_mma(const char* __restrict__ A, const char* __restrict__ B,
         const float* __restrict__ bias, void* __restrict__ Cv,
         int NCc, int TA, int TB, int ldA, int ldB,
         int Ncols, long long sAb, long long sBb, long long sC,
         float scale, int emit)
{
    extern __shared__ char sm[];
    A += (long long)blockIdx.z * sAb;
    B += (long long)blockIdx.z * sBb;

    const int tid = threadIdx.x, wid = tid >> 5, lane = tid & 31;
    const int row0 = blockIdx.y * 128, col0 = blockIdx.x * 128;
    const int wm = wid & 3, wn = wid >> 2;

    uint32_t sbase = (smem_u32(sm) + 127u) & ~127u;

    // loader: row = tid>>1, 4 x 16B chunks starting at (tid&1)*4
    const int lrow = tid >> 1;
    const int lc0 = (tid & 1) * 4;
    const char* gA = A + (long long)(row0 + lrow) * ldA;
    const char* gB = B + (long long)(col0 + lrow) * ldB;
    uint32_t swo[4];
#pragma unroll
    for (int q = 0; q < 4; q++) {
        uint32_t off = (uint32_t)lrow * 128u + (lc0 + q) * 16u;
        swo[q] = SWZ128(off);
    }

    // prologue: chunks 0,1 -> stages 0,1 (off = c*128 valid for c<min(TA,TB))
#pragma unroll
    for (int s = 0; s < 2; s++) {
        uint32_t aA = sbase + s * STAGE_BYTES;
        uint32_t aB = aA + 16384;
        int kb = s * 128;
#pragma unroll
        for (int q = 0; q < 4; q++) {
            cp16(aA + swo[q], gA + kb + (lc0 + q) * 16);
            cp16(aB + swo[q], gB + kb + (lc0 + q) * 16);
        }
        CP_COMMIT();
    }

    float acc[2][8][4];
#pragma unroll
    for (int mi = 0; mi < 2; mi++)
#pragma unroll
        for (int ni = 0; ni < 8; ni++)
#pragma unroll
            for (int r = 0; r < 4; r++) acc[mi][ni][r] = 0.f;

    const int fr = lane & 15;
    const int fk = (lane >> 4) * 16;
    uint32_t arow[2], brow[4];
#pragma unroll
    for (int mi = 0; mi < 2; mi++) arow[mi] = (uint32_t)(wm * 32 + mi * 16 + fr) * 128u;
#pragma unroll
    for (int bi = 0; bi < 4; bi++) brow[bi] = (uint32_t)(wn * 64 + bi * 16 + fr) * 128u;

    int st_c = 0, st_n = 2;
    for (int c = 0; c < NCc; c++) {
        CP_WAIT1();               // chunk c resident
        __syncthreads();          // chunk c-1 consumed by all warps (stage st_n free)

        if (c + 2 < NCc) {
            uint32_t aA = sbase + st_n * STAGE_BYTES;
            uint32_t aB = aA + 16384;
            int c2 = c + 2;
            int oA = ((c2 < TA) ? c2 : c2 - TA) * 128;
            int oB = ((c2 < TB) ? c2 : c2 - TB) * 128;
#pragma unroll
            for (int q = 0; q < 4; q++) {
                cp16(aA + swo[q], gA + oA + (lc0 + q) * 16);
                cp16(aB + swo[q], gB + oB + (lc0 + q) * 16);
            }
        }
        CP_COMMIT();

        uint32_t aA = sbase + st_c * STAGE_BYTES;
        uint32_t aB = aA + 16384;

        uint32_t af[2][2][4];
        uint32_t bfA[2][4], bfB[2][4];

#pragma unroll
        for (int mi = 0; mi < 2; mi++)
            ldmx4(af[0][mi], aA + SWZ128(arow[mi] + fk));
#pragma unroll
        for (int p = 0; p < 2; p++)
            ldmx4(bfA[p], aB + SWZ128(brow[p] + fk));

#pragma unroll
        for (int ks = 0; ks < 4; ks++) {
            const int cur = ks & 1;
            const int kbyte = ks * 32 + fk;
            const int knext = kbyte + 32;

#pragma unroll
            for (int p = 0; p < 2; p++)
                ldmx4(bfB[p], aB + SWZ128(brow[2 + p] + kbyte));
            if (ks < 3) {
#pragma unroll
                for (int mi = 0; mi < 2; mi++)
                    ldmx4(af[cur ^ 1][mi], aA + SWZ128(arow[mi] + knext));
            }
#pragma unroll
            for (int p = 0; p < 2; p++)
#pragma unroll
                for (int mi = 0; mi < 2; mi++) {
                    mma16816<FP16>(acc[mi][2 * p + 0], af[cur][mi], bfA[p][0], bfA[p][2]);
                    mma16816<FP16>(acc[mi][2 * p + 1], af[cur][mi], bfA[p][1], bfA[p][3]);
                }
            if (ks < 3) {
#pragma unroll
                for (int p = 0; p < 2; p++)
                    ldmx4(bfA[p], aB + SWZ128(brow[p] + knext));
            }
#pragma unroll
            for (int p = 0; p < 2; p++)
#pragma unroll
                for (int mi = 0; mi < 2; mi++) {
                    mma16816<FP16>(acc[mi][4 + 2 * p + 0], af[cur][mi], bfB[p][0], bfB[p][2]);
                    mma16816<FP16>(acc[mi][4 + 2 * p + 1], af[cur][mi], bfB[p][1], bfB[p][3]);
                }
        }
        st_c = (st_c == 2) ? 0 : st_c + 1;
        st_n = (st_n == 2) ? 0 : st_n + 1;
    }

    // epilogue
#pragma unroll
    for (int mi = 0; mi < 2; mi++) {
        int r = row0 + wm * 32 + mi * 16 + (lane >> 2);
#pragma unroll
        for (int ni = 0; ni < 8; ni++) {
            int cc = col0 + wn * 64 + ni * 8 + (lane & 3) * 2;
            float b0 = bias ? bias[cc] : 0.f;
            float b1 = bias ? bias[cc + 1] : 0.f;
            float x0 = acc[mi][ni][0] * scale + b0;
            float y0 = acc[mi][ni][1] * scale + b1;
            float x1 = acc[mi][ni][2] * scale + b0;
            float y1 = acc[mi][ni][3] * scale + b1;
            if (emit == 0) {
                float* C = (float*)Cv + (long long)blockIdx.z * sC;
                float2 v0 = {x0, y0}, v1 = {x1, y1};
                *(float2*)(C + (long long)r * Ncols + cc) = v0;
                *(float2*)(C + (long long)(r + 8) * Ncols + cc) = v1;
            } else if (emit == 1) {
                __nv_bfloat16* C = (__nv_bfloat16*)Cv;
                store_split2_bf16(C + (long long)r * K2 + cc, x0, y0);
                store_split2_bf16(C + (long long)(r + 8) * K2 + cc, x1, y1);
            } else if (emit == 2) {
                __half* C = (__half*)Cv;
                __half2 h0, h1;
                h0.x = __float2half(x0); h0.y = __float2half(y0);
                h1.x = __float2half(x1); h1.y = __float2half(y1);
                *(__half2*)(C + (long long)r * EE + cc) = h0;
                *(__half2*)(C + (long long)(r + 8) * EE + cc) = h1;
            } else {
                __half* C = (__half*)Cv;
                store_split2_f16(C + (long long)r * K2 + cc, x0, y0);
                store_split2_f16(C + (long long)(r + 8) * K2 + cc, x1, y1);
            }
        }
    }
}

// ================= elementwise kernels =================
// fp32 -> canonical bf16 split [R,4096]
__global__ void __launch_bounds__(256) split3(const float* __restrict__ X,
                                              __nv_bfloat16* __restrict__ Y, int n) {
    int i = blockIdx.x * 256 + threadIdx.x;
    if (i >= n) return;
    int r = i >> 11, k = i & 2047;
    float x = X[i];
    __nv_bfloat16 h = __float2bfloat16(x);
    __nv_bfloat16 l = __float2bfloat16(x - __bfloat162float(h));
    __nv_bfloat16* yr = Y + (size_t)r * K2;
    yr[k] = h;
    yr[2048 + k] = l;
}

// transpose + fp16 canonical split: Y16[r, :] = split(W[:, r])
__global__ void __launch_bounds__(256) split3t_f16(const float* __restrict__ W,
                                                   __half* __restrict__ Y) {
    __shared__ float t[32][33];
    int tx = threadIdx.x & 31, ty = threadIdx.x >> 5;
    int cbase = blockIdx.x * 32;
    int rbase = blockIdx.y * 32;
#pragma unroll
    for (int j = 0; j < 4; j++)
        t[ty + j * 8][tx] = W[(size_t)(rbase + ty + j * 8) * EE + cbase + tx];
    __syncthreads();
#pragma unroll
    for (int j = 0; j < 4; j++) {
        int r = cbase + ty + j * 8;
        int k = rbase + tx;
        float x = t[tx][ty + j * 8];
        __half h = __float2half(x);
        __half l = __float2half(x - __half2float(h));
        __half* yr = Y + (size_t)r * K2;
        yr[k] = h;
        yr[2048 + k] = l;
    }
}

// build XR fp32 + fp16 canonical split in one pass
__global__ void __launch_bounds__(256) build_xr_split(const float* __restrict__ x,
                                                      float* __restrict__ xr,
                                                      __half* __restrict__ xr16) {
    __shared__ float s[TT * 129];
    int bn = blockIdx.x;
    int b = bn >> 9, n = bn & 511;
    for (int i = threadIdx.x; i < TT * FF; i += 256) {
        int t = i >> 7, f = i & 127;
        s[t * 129 + f] = x[((size_t)(t * BB + b) * NN + n) * FF + f];
    }
    __syncthreads();
    for (int e = threadIdx.x; e < EE; e += 256) {
        int t = e & 15, f = e >> 4;
        float v = s[t * 129 + f];
        xr[(size_t)bn * EE + e] = v;
        __half h = __float2half(v);
        __half l = __float2half(v - __half2float(h));
        size_t rb = (size_t)bn * K2 + e;
        xr16[rb] = h;
        xr16[rb + 2048] = l;
    }
}

__global__ void __launch_bounds__(256) wkbq_kernel(const float* __restrict__ Wk,
                                                   const float* __restrict__ bq,
                                                   float* __restrict__ w2) {
    int e = blockIdx.x * 256 + threadIdx.x;
    float s = 0.f;
    for (int d = 0; d < EE; d++) s += Wk[(size_t)d * EE + e] * bq[d];
    w2[e] = s;
}
__global__ void __launch_bounds__(256) xrw2_kernel(const float* __restrict__ XR,
                                                   const float* __restrict__ w2,
                                                   float* __restrict__ v, float scale) {
    int g = blockIdx.x * 8 + (threadIdx.x >> 5);
    int lane = threadIdx.x & 31;
    const float* r = XR + (size_t)g * EE;
    float s = 0.f;
    for (int e = lane; e < EE; e += 32) s += r[e] * w2[e];
#pragma unroll
    for (int o = 16; o; o >>= 1) s += __shfl_xor_sync(0xffffffffu, s, o);
    if (lane == 0) v[g] = s * scale;
}

__global__ void __launch_bounds__(128) softmax_rows(float* __restrict__ att,
                                                    const float* __restrict__ vadd) {
    size_t row = blockIdx.x;
    int b = (int)(row >> 9);
    float4* p = (float4*)(att + row * 512);
    const float4* vv = (const float4*)(vadd + (size_t)b * 512);
    float4 v = p[threadIdx.x];
    float4 a = vv[threadIdx.x];
    v.x += a.x; v.y += a.y; v.z += a.z; v.w += a.w;
    float m = fmaxf(fmaxf(v.x, v.y), fmaxf(v.z, v.w));
#pragma unroll
    for (int o = 16; o; o >>= 1) m = fmaxf(m, __shfl_xor_sync(0xffffffffu, m, o));
    __shared__ float sm[4];
    if ((threadIdx.x & 31) == 0) sm[threadIdx.x >> 5] = m;
    __syncthreads();
    m = fmaxf(fmaxf(sm[0], sm[1]), fmaxf(sm[2], sm[3]));
    v.x = __expf(v.x - m); v.y = __expf(v.y - m);
    v.z = __expf(v.z - m); v.w = __expf(v.w - m);
    float s = v.x + v.y + v.z + v.w;
#pragma unroll
    for (int o = 16; o; o >>= 1) s += __shfl_xor_sync(0xffffffffu, s, o);
    __shared__ float ss[4];
    if ((threadIdx.x & 31) == 0) ss[threadIdx.x >> 5] = s;
    __syncthreads();
    s = ss[0] + ss[1] + ss[2] + ss[3];
    float inv = 1.f / s;
    v.x *= inv; v.y *= inv; v.z *= inv; v.w *= inv;
    p[threadIdx.x] = v;
}

__global__ void __launch_bounds__(512) abar_kernel(const float* __restrict__ att,
                                                   float* __restrict__ abar) {
    int bg = blockIdx.x;
    int b = bg >> 4, g = bg & 15;
    const float* bse = att + ((size_t)b * 512 + g * 32) * 512;
    int j = threadIdx.x;
    float s = 0.f;
#pragma unroll 8
    for (int r = 0; r < 32; r++) s += bse[(size_t)r * 512 + j];
    abar[(size_t)bg * 512 + j] = s * (1.f / 32.f);
}

__global__ void __launch_bounds__(128) zbar_split(const float* __restrict__ abar,
                                                  const float* __restrict__ XR,
                                                  __nv_bfloat16* __restrict__ Zs) {
    int b = blockIdx.y;
    int col0 = blockIdx.x * 128;
    __shared__ float sA[16 * 512];
    for (int i = threadIdx.x; i < 16 * 512; i += 128)
        sA[i] = abar[(size_t)b * 16 * 512 + i];
    __syncthreads();
    float acc[16];
#pragma unroll
    for (int g = 0; g < 16; g++) acc[g] = 0.f;
    const float* vb = XR + (size_t)b * 512 * EE + col0 + threadIdx.x;
    for (int l = 0; l < 512; l++) {
        float vv = vb[(size_t)l * EE];
#pragma unroll
        for (int g = 0; g < 16; g++) acc[g] = fmaf(sA[g * 512 + l], vv, acc[g]);
    }
#pragma unroll
    for (int g = 0; g < 16; g++) {
        float v = acc[g];
        __nv_bfloat16 h = __float2bfloat16(v);
        __nv_bfloat16 l2 = __float2bfloat16(v - __bfloat162float(h));
        size_t rb = ((size_t)b * 16 + g) * K2 + col0 + threadIdx.x;
        Zs[rb] = h;
        Zs[rb + 2048] = l2;
    }
}

__global__ void __launch_bounds__(256) final_kernel(const float* __restrict__ x,
                                                    const float* __restrict__ outbar,
                                                    float* __restrict__ out) {
    int idx = blockIdx.x * 256 + threadIdx.x;
    int f = idx & 127;
    int i = (idx >> 7) & 511;
    int t = idx >> 16;
    const float* px = x + (size_t)t * (BB * NN * FF) + (size_t)i * FF + f;
    float s = 0.f;
#pragma unroll 8
    for (int b = 0; b < 32; b++) s += px[(size_t)b * (NN * FF)];
    out[idx] = s * (1.f / 32.f) + outbar[(size_t)i * EE + t * FF + f];
}

// ---------------- launcher ----------------
extern "C" void kernel_launch(void* const* d_in, const int* in_sizes, int n_in,
                              void* d_out, int out_size) {
    const float* x   = (const float*)d_in[0];
    const float* Wq  = (const float*)d_in[1];
    const float* bq  = (const float*)d_in[2];
    const float* Wk  = (const float*)d_in[3];
    const float* Wv  = (const float*)d_in[5];
    const float* bv  = (const float*)d_in[6];
    const float* Wfc = (const float*)d_in[7];
    const float* bfc = (const float*)d_in[8];
    float* out = (float*)d_out;

    float *pXR, *pAtt, *pAbar, *pOutBar, *pw2, *pv;
    __half *pXR16, *pY16, *pWkT16, *pWqT16, *pM3h;
    __nv_bfloat16 *pWvs, *pWfcs, *pZs, *pObars;
    cudaGetSymbolAddress((void**)&pXR, g_XR);
    cudaGetSymbolAddress((void**)&pAbar, g_Abar);
    cudaGetSymbolAddress((void**)&pOutBar, g_OutBar);
    cudaGetSymbolAddress((void**)&pw2, g_w2);
    cudaGetSymbolAddress((void**)&pv, g_vvec);
    cudaGetSymbolAddress((void**)&pXR16, g_XR16);
    cudaGetSymbolAddress((void**)&pY16, g_Y16);
    cudaGetSymbolAddress((void**)&pWkT16, g_WkT16);
    cudaGetSymbolAddress((void**)&pWqT16, g_WqT16);
    cudaGetSymbolAddress((void**)&pM3h, g_M3h);
    cudaGetSymbolAddress((void**)&pWvs, g_Wvs);
    cudaGetSymbolAddress((void**)&pWfcs, g_Wfcs);
    cudaGetSymbolAddress((void**)&pZs, g_Zs);
    cudaGetSymbolAddress((void**)&pObars, g_Obars);

    if (out_size >= RES_ELEMS + ATT_ELEMS) pAtt = out + RES_ELEMS;
    else cudaGetSymbolAddress((void**)&pAtt, g_Att);

    cudaFuncSetAttribute(gemm_mma<true>, cudaFuncAttributeMaxDynamicSharedMemorySize, DSM_BYTES);
    cudaFuncSetAttribute(gemm_mma<false>, cudaFuncAttributeMaxDynamicSharedMemorySize, DSM_BYTES);

    const float scale = rsqrtf((float)EE);
    const int nW = EE * EE;

    // 1) XR fp32 + fp16 split (single pass over x)
    build_xr_split<<<MROWS, 256>>>(x, pXR, pXR16);

    // 2) M3 = Wk^T Wq (fp16 2-term, K=4096) -> fp16 single
    dim3 gT(64, 64);
    split3t_f16<<<gT, 256>>>(Wk, pWkT16);
    split3t_f16<<<gT, 256>>>(Wq, pWqT16);
    dim3 gM3(EE / 128, EE / 128);
    gemm_mma<true><<<gM3, 256, DSM_BYTES>>>((const char*)pWkT16, (const char*)pWqT16,
        nullptr, pM3h, 64, 64, 32, 8192, 8192, 0, 0, 0, 0, 1.f, 2);

    // 3) Y = XR @ M3^T (fp16 2-term) -> fp16 canonical split
    dim3 gY(EE / 128, MROWS / 128);
    gemm_mma<true><<<gY, 256, DSM_BYTES>>>((const char*)pXR16, (const char*)pM3h,
        nullptr, pY16, 64, 64, 32, 8192, 4096, 0, 0, 0, 0, 1.f, 3);

    // 4) energy = scale * Y_b XR_b^T (fp16 2-term, batched over 32) -> fp32
    dim3 gE(512 / 128, 512 / 128, 32);
    gemm_mma<true><<<gE, 256, DSM_BYTES>>>((const char*)pY16, (const char*)pXR16,
        nullptr, pAtt, 64, 64, 32, 8192, 8192,
        512, (long long)512 * 8192, (long long)512 * 8192, (long long)512 * 512,
        scale, 0);

    // 5) bias column vector; softmax with +v[j]
    wkbq_kernel<<<EE / 256, 256>>>(Wk, bq, pw2);
    xrw2_kernel<<<MROWS / 8, 256>>>(pXR, pw2, pv, scale);
    softmax_rows<<<32 * 512, 128>>>(pAtt, pv);

    // 6) Abar, Z = Abar @ XR (bf16 canonical split emitted)
    abar_kernel<<<512, 512>>>(pAtt, pAbar);
    dim3 gZ(EE / 128, 32);
    zbar_split<<<gZ, 128>>>(pAbar, pXR, pZs);

    // 7) Obar = Z @ Wv^T + bv (bf16 3-term, precise) -> bf16 canonical split
    split3<<<(nW + 255) / 256, 256>>>(Wv, pWvs, nW);
    dim3 gOb(EE / 128, 512 / 128);
    gemm_mma<false><<<gOb, 256, DSM_BYTES>>>((const char*)pZs, (const char*)pWvs,
        bv, pObars, 96, 64, 32, 8192, 8192, 0, 0, 0, 0, 1.f, 1);

    // 8) OutBar = Obar @ Wfc^T + bfc (bf16 3-term) -> fp32
    split3<<<(nW + 255) / 256, 256>>>(Wfc, pWfcs, nW);
    gemm_mma<false><<<gOb, 256, DSM_BYTES>>>((const char*)pObars, (const char*)pWfcs,
        bfc, pOutBar, 96, 64, 32, 8192, 8192, EE, 0, 0, 0, 1.f, 0);

    // 9) final output
    final_kernel<<<RES_ELEMS / 256, 256>>>(x, pOutBar, out);
}

// round 14
// speedup vs baseline: 2.0740x; 1.4048x over previous
#include <cuda_runtime.h>
#include <cuda_bf16.h>
#include <cuda_fp16.h>
#include <math.h>
#include <stdint.h>

// Problem dims
#define TT 16
#define BB 32
#define NN 512
#define FF 128
#define EE 2048            // F*T
#define K2 4096            // split row length (hi|lo) in elems
#define MROWS 16384        // B*N
#define ATT_ELEMS (32*512*512)
#define RES_ELEMS (16*512*128)

// ---------------- device scratch ----------------
__device__ float g_XR[(size_t)MROWS * EE];
__device__ float g_Att[(size_t)ATT_ELEMS];
__device__ float g_Abar[(size_t)512 * 512];
__device__ float g_OutBar[(size_t)512 * EE];
__device__ float g_w2[EE];
__device__ float g_vvec[MROWS];

// fp16 buffers
__device__ __half g_XR16[(size_t)MROWS * K2];     // split [hi|lo]
__device__ __half g_Y16 [(size_t)MROWS * K2];     // split [hi|lo]
__device__ __half g_WkT16[(size_t)EE * K2];       // split
__device__ __half g_WqT16[(size_t)EE * K2];       // split
__device__ __half g_M3h[(size_t)EE * EE];         // single
__device__ __half g_Wv16 [(size_t)EE * EE];       // single
__device__ __half g_Wfc16[(size_t)EE * EE];       // single
__device__ __half g_Z16  [(size_t)512 * EE];      // single
__device__ __half g_Obar16[(size_t)512 * EE];     // single

// ================= helpers =================
__device__ __forceinline__ uint32_t smem_u32(const void* p) {
    uint32_t a;
    asm("{ .reg .u64 t; cvta.to.shared.u64 t, %1; cvt.u32.u64 %0, t; }" : "=r"(a) : "l"(p));
    return a;
}
#define SWZ128(off) ((off) ^ (((off) >> 3) & 0x70))

__device__ __forceinline__ void cp16(uint32_t s, const void* g) {
    asm volatile("cp.async.cg.shared.global [%0], [%1], 16;" :: "r"(s), "l"(g));
}
#define CP_COMMIT() asm volatile("cp.async.commit_group;" ::: "memory")
#define CP_WAIT1()  asm volatile("cp.async.wait_group 1;" ::: "memory")

__device__ __forceinline__ void ldmx4(uint32_t* f, uint32_t addr) {
    asm volatile("ldmatrix.sync.aligned.m8n8.x4.shared.b16 {%0,%1,%2,%3}, [%4];"
        : "=r"(f[0]), "=r"(f[1]), "=r"(f[2]), "=r"(f[3]) : "r"(addr));
}
__device__ __forceinline__ void mma16816(float* d, const uint32_t* a,
                                         uint32_t b0, uint32_t b1) {
    asm volatile("mma.sync.aligned.m16n8k16.row.col.f32.f16.f16.f32 "
        "{%0,%1,%2,%3}, {%4,%5,%6,%7}, {%8,%9}, {%0,%1,%2,%3};"
        : "+f"(d[0]), "+f"(d[1]), "+f"(d[2]), "+f"(d[3])
        : "r"(a[0]), "r"(a[1]), "r"(a[2]), "r"(a[3]), "r"(b0), "r"(b1));
}
__device__ __forceinline__ void store_split2_f16(__half* p, float x, float y) {
    __half2 h, l;
    h.x = __float2half(x); h.y = __float2half(y);
    l.x = __float2half(x - __half2float(h.x));
    l.y = __float2half(y - __half2float(h.y));
    *(__half2*)p = h;
    *(__half2*)(p + 2048) = l;
}

#define STAGE_BYTES 32768      // A 16KB + B 16KB (128 rows x 128B per chunk)
#define DSM_BYTES (3 * STAGE_BYTES + 128)

// ================= fp16 mma.sync NT GEMM ========================================
// Virtual K = NCc chunks of 64 elems (128B). Chunk c reads A row offset
// (c<TA ? c : c-TA)*128 bytes, B row offset (c<TB ? c : c-TB)*128.
//   2-term: NCc=64, TA=64 ([hi|lo]), TB=32 (hi twice) -> (Ah+Al)Bh
//   1-term: NCc=32, TA=TB=32 -> Ah·Bh
// emit: 0 fp32 C (ld Ncols, batch sC elems); 2 fp16 single (ld 2048);
//       3 fp16 split (ld 4096)
__global__ void __launch_bounds__(256, 2)
gemm_mma(const char* __restrict__ A, const char* __restrict__ B,
         const float* __restrict__ bias, void* __restrict__ Cv,
         int NCc, int TA, int TB, int ldA, int ldB,
         int Ncols, long long sAb, long long sBb, long long sC,
         float scale, int emit)
{
    extern __shared__ char sm[];
    A += (long long)blockIdx.z * sAb;
    B += (long long)blockIdx.z * sBb;

    const int tid = threadIdx.x, wid = tid >> 5, lane = tid & 31;
    const int row0 = blockIdx.y * 128, col0 = blockIdx.x * 128;
    const int wm = wid & 3, wn = wid >> 2;

    uint32_t sbase = (smem_u32(sm) + 127u) & ~127u;

    // loader: row = tid>>1, 4 x 16B chunks starting at (tid&1)*4
    const int lrow = tid >> 1;
    const int lc0 = (tid & 1) * 4;
    const char* gA = A + (long long)(row0 + lrow) * ldA;
    const char* gB = B + (long long)(col0 + lrow) * ldB;
    uint32_t swo[4];
#pragma unroll
    for (int q = 0; q < 4; q++) {
        uint32_t off = (uint32_t)lrow * 128u + (lc0 + q) * 16u;
        swo[q] = SWZ128(off);
    }

    // prologue: chunks 0,1 -> stages 0,1 (off = c*128 valid while c < min(TA,TB))
#pragma unroll
    for (int s = 0; s < 2; s++) {
        uint32_t aA = sbase + s * STAGE_BYTES;
        uint32_t aB = aA + 16384;
        int kb = s * 128;
#pragma unroll
        for (int q = 0; q < 4; q++) {
            cp16(aA + swo[q], gA + kb + (lc0 + q) * 16);
            cp16(aB + swo[q], gB + kb + (lc0 + q) * 16);
        }
        CP_COMMIT();
    }

    float acc[2][8][4];
#pragma unroll
    for (int mi = 0; mi < 2; mi++)
#pragma unroll
        for (int ni = 0; ni < 8; ni++)
#pragma unroll
            for (int r = 0; r < 4; r++) acc[mi][ni][r] = 0.f;

    const int fr = lane & 15;
    const int fk = (lane >> 4) * 16;
    uint32_t arow[2], brow[4];
#pragma unroll
    for (int mi = 0; mi < 2; mi++) arow[mi] = (uint32_t)(wm * 32 + mi * 16 + fr) * 128u;
#pragma unroll
    for (int bi = 0; bi < 4; bi++) brow[bi] = (uint32_t)(wn * 64 + bi * 16 + fr) * 128u;

    int st_c = 0, st_n = 2;
    for (int c = 0; c < NCc; c++) {
        CP_WAIT1();               // chunk c resident
        __syncthreads();          // chunk c-1 consumed by all warps (stage st_n free)

        if (c + 2 < NCc) {
            uint32_t aA = sbase + st_n * STAGE_BYTES;
            uint32_t aB = aA + 16384;
            int c2 = c + 2;
            int oA = ((c2 < TA) ? c2 : c2 - TA) * 128;
            int oB = ((c2 < TB) ? c2 : c2 - TB) * 128;
#pragma unroll
            for (int q = 0; q < 4; q++) {
                cp16(aA + swo[q], gA + oA + (lc0 + q) * 16);
                cp16(aB + swo[q], gB + oB + (lc0 + q) * 16);
            }
        }
        CP_COMMIT();

        uint32_t aA = sbase + st_c * STAGE_BYTES;
        uint32_t aB = aA + 16384;

        uint32_t af[2][2][4];
        uint32_t bfA[2][4], bfB[2][4];

#pragma unroll
        for (int mi = 0; mi < 2; mi++)
            ldmx4(af[0][mi], aA + SWZ128(arow[mi] + fk));
#pragma unroll
        for (int p = 0; p < 2; p++)
            ldmx4(bfA[p], aB + SWZ128(brow[p] + fk));

#pragma unroll
        for (int ks = 0; ks < 4; ks++) {
            const int cur = ks & 1;
            const int kbyte = ks * 32 + fk;
            const int knext = kbyte + 32;

#pragma unroll
            for (int p = 0; p < 2; p++)
                ldmx4(bfB[p], aB + SWZ128(brow[2 + p] + kbyte));
            if (ks < 3) {
#pragma unroll
                for (int mi = 0; mi < 2; mi++)
                    ldmx4(af[cur ^ 1][mi], aA + SWZ128(arow[mi] + knext));
            }
#pragma unroll
            for (int p = 0; p < 2; p++)
#pragma unroll
                for (int mi = 0; mi < 2; mi++) {
                    mma16816(acc[mi][2 * p + 0], af[cur][mi], bfA[p][0], bfA[p][2]);
                    mma16816(acc[mi][2 * p + 1], af[cur][mi], bfA[p][1], bfA[p][3]);
                }
            if (ks < 3) {
#pragma unroll
                for (int p = 0; p < 2; p++)
                    ldmx4(bfA[p], aB + SWZ128(brow[p] + knext));
            }
#pragma unroll
            for (int p = 0; p < 2; p++)
#pragma unroll
                for (int mi = 0; mi < 2; mi++) {
                    mma16816(acc[mi][4 + 2 * p + 0], af[cur][mi], bfB[p][0], bfB[p][2]);
                    mma16816(acc[mi][4 + 2 * p + 1], af[cur][mi], bfB[p][1], bfB[p][3]);
                }
        }
        st_c = (st_c == 2) ? 0 : st_c + 1;
        st_n = (st_n == 2) ? 0 : st_n + 1;
    }

    // epilogue
#pragma unroll
    for (int mi = 0; mi < 2; mi++) {
        int r = row0 + wm * 32 + mi * 16 + (lane >> 2);
#pragma unroll
        for (int ni = 0; ni < 8; ni++) {
            int cc = col0 + wn * 64 + ni * 8 + (lane & 3) * 2;
            float b0 = bias ? bias[cc] : 0.f;
            float b1 = bias ? bias[cc + 1] : 0.f;
            float x0 = acc[mi][ni][0] * scale + b0;
            float y0 = acc[mi][ni][1] * scale + b1;
            float x1 = acc[mi][ni][2] * scale + b0;
            float y1 = acc[mi][ni][3] * scale + b1;
            if (emit == 0) {
                float* C = (float*)Cv + (long long)blockIdx.z * sC;
                float2 v0 = {x0, y0}, v1 = {x1, y1};
                *(float2*)(C + (long long)r * Ncols + cc) = v0;
                *(float2*)(C + (long long)(r + 8) * Ncols + cc) = v1;
            } else if (emit == 2) {
                __half* C = (__half*)Cv;
                __half2 h0, h1;
                h0.x = __float2half(x0); h0.y = __float2half(y0);
                h1.x = __float2half(x1); h1.y = __float2half(y1);
                *(__half2*)(C + (long long)r * EE + cc) = h0;
                *(__half2*)(C + (long long)(r + 8) * EE + cc) = h1;
            } else {
                __half* C = (__half*)Cv;
                store_split2_f16(C + (long long)r * K2 + cc, x0, y0);
                store_split2_f16(C + (long long)(r + 8) * K2 + cc, x1, y1);
            }
        }
    }
}

// ================= elementwise kernels =================
// fp32 -> fp16 single
__global__ void __launch_bounds__(256) cast_f16(const float* __restrict__ X,
                                                __half* __restrict__ Y, int n) {
    int i = blockIdx.x * 256 + threadIdx.x;
    if (i < n) Y[i] = __float2half(X[i]);
}

// transpose + fp16 split: Y16[r, :] = split(W[:, r])
__global__ void __launch_bounds__(256) split3t_f16(const float* __restrict__ W,
                                                   __half* __restrict__ Y) {
    __shared__ float t[32][33];
    int tx = threadIdx.x & 31, ty = threadIdx.x >> 5;
    int cbase = blockIdx.x * 32;
    int rbase = blockIdx.y * 32;
#pragma unroll
    for (int j = 0; j < 4; j++)
        t[ty + j * 8][tx] = W[(size_t)(rbase + ty + j * 8) * EE + cbase + tx];
    __syncthreads();
#pragma unroll
    for (int j = 0; j < 4; j++) {
        int r = cbase + ty + j * 8;
        int k = rbase + tx;
        float x = t[tx][ty + j * 8];
        __half h = __float2half(x);
        __half l = __float2half(x - __half2float(h));
        __half* yr = Y + (size_t)r * K2;
        yr[k] = h;
        yr[2048 + k] = l;
    }
}

// build XR fp32 + fp16 split in one pass
__global__ void __launch_bounds__(256) build_xr_split(const float* __restrict__ x,
                                                      float* __restrict__ xr,
                                                      __half* __restrict__ xr16) {
    __shared__ float s[TT * 129];
    int bn = blockIdx.x;
    int b = bn >> 9, n = bn & 511;
    for (int i = threadIdx.x; i < TT * FF; i += 256) {
        int t = i >> 7, f = i & 127;
        s[t * 129 + f] = x[((size_t)(t * BB + b) * NN + n) * FF + f];
    }
    __syncthreads();
    for (int e = threadIdx.x; e < EE; e += 256) {
        int t = e & 15, f = e >> 4;
        float v = s[t * 129 + f];
        xr[(size_t)bn * EE + e] = v;
        __half h = __float2half(v);
        __half l = __float2half(v - __half2float(h));
        size_t rb = (size_t)bn * K2 + e;
        xr16[rb] = h;
        xr16[rb + 2048] = l;
    }
}

__global__ void __launch_bounds__(256) wkbq_kernel(const float* __restrict__ Wk,
                                                   const float* __restrict__ bq,
                                                   float* __restrict__ w2) {
    int e = blockIdx.x * 256 + threadIdx.x;
    float s = 0.f;
    for (int d = 0; d < EE; d++) s += Wk[(size_t)d * EE + e] * bq[d];
    w2[e] = s;
}
__global__ void __launch_bounds__(256) xrw2_kernel(const float* __restrict__ XR,
                                                   const float* __restrict__ w2,
                                                   float* __restrict__ v, float scale) {
    int g = blockIdx.x * 8 + (threadIdx.x >> 5);
    int lane = threadIdx.x & 31;
    const float* r = XR + (size_t)g * EE;
    float s = 0.f;
    for (int e = lane; e < EE; e += 32) s += r[e] * w2[e];
#pragma unroll
    for (int o = 16; o; o >>= 1) s += __shfl_xor_sync(0xffffffffu, s, o);
    if (lane == 0) v[g] = s * scale;
}

__global__ void __launch_bounds__(128) softmax_rows(float* __restrict__ att,
                                                    const float* __restrict__ vadd) {
    size_t row = blockIdx.x;
    int b = (int)(row >> 9);
    float4* p = (float4*)(att + row * 512);
    const float4* vv = (const float4*)(vadd + (size_t)b * 512);
    float4 v = p[threadIdx.x];
    float4 a = vv[threadIdx.x];
    v.x += a.x; v.y += a.y; v.z += a.z; v.w += a.w;
    float m = fmaxf(fmaxf(v.x, v.y), fmaxf(v.z, v.w));
#pragma unroll
    for (int o = 16; o; o >>= 1) m = fmaxf(m, __shfl_xor_sync(0xffffffffu, m, o));
    __shared__ float sm[4];
    if ((threadIdx.x & 31) == 0) sm[threadIdx.x >> 5] = m;
    __syncthreads();
    m = fmaxf(fmaxf(sm[0], sm[1]), fmaxf(sm[2], sm[3]));
    v.x = __expf(v.x - m); v.y = __expf(v.y - m);
    v.z = __expf(v.z - m); v.w = __expf(v.w - m);
    float s = v.x + v.y + v.z + v.w;
#pragma unroll
    for (int o = 16; o; o >>= 1) s += __shfl_xor_sync(0xffffffffu, s, o);
    __shared__ float ss[4];
    if ((threadIdx.x & 31) == 0) ss[threadIdx.x >> 5] = s;
    __syncthreads();
    s = ss[0] + ss[1] + ss[2] + ss[3];
    float inv = 1.f / s;
    v.x *= inv; v.y *= inv; v.z *= inv; v.w *= inv;
    p[threadIdx.x] = v;
}

__global__ void __launch_bounds__(512) abar_kernel(const float* __restrict__ att,
                                                   float* __restrict__ abar) {
    int bg = blockIdx.x;
    int b = bg >> 4, g = bg & 15;
    const float* bse = att + ((size_t)b * 512 + g * 32) * 512;
    int j = threadIdx.x;
    float s = 0.f;
#pragma unroll 8
    for (int r = 0; r < 32; r++) s += bse[(size_t)r * 512 + j];
    abar[(size_t)bg * 512 + j] = s * (1.f / 32.f);
}

// Z = Abar_b @ XR_b -> fp16 single
__global__ void __launch_bounds__(128) zbar_f16(const float* __restrict__ abar,
                                                const float* __restrict__ XR,
                                                __half* __restrict__ Z16) {
    int b = blockIdx.y;
    int col0 = blockIdx.x * 128;
    __shared__ float sA[16 * 512];
    for (int i = threadIdx.x; i < 16 * 512; i += 128)
        sA[i] = abar[(size_t)b * 16 * 512 + i];
    __syncthreads();
    float acc[16];
#pragma unroll
    for (int g = 0; g < 16; g++) acc[g] = 0.f;
    const float* vb = XR + (size_t)b * 512 * EE + col0 + threadIdx.x;
    for (int l = 0; l < 512; l++) {
        float vv = vb[(size_t)l * EE];
#pragma unroll
        for (int g = 0; g < 16; g++) acc[g] = fmaf(sA[g * 512 + l], vv, acc[g]);
    }
#pragma unroll
    for (int g = 0; g < 16; g++)
        Z16[((size_t)b * 16 + g) * EE + col0 + threadIdx.x] = __float2half(acc[g]);
}

__global__ void __launch_bounds__(256) final_kernel(const float* __restrict__ x,
                                                    const float* __restrict__ outbar,
                                                    float* __restrict__ out) {
    int idx = blockIdx.x * 256 + threadIdx.x;
    int f = idx & 127;
    int i = (idx >> 7) & 511;
    int t = idx >> 16;
    const float* px = x + (size_t)t * (BB * NN * FF) + (size_t)i * FF + f;
    float s = 0.f;
#pragma unroll 8
    for (int b = 0; b < 32; b++) s += px[(size_t)b * (NN * FF)];
    out[idx] = s * (1.f / 32.f) + outbar[(size_t)i * EE + t * FF + f];
}

// ---------------- launcher ----------------
extern "C" void kernel_launch(void* const* d_in, const int* in_sizes, int n_in,
                              void* d_out, int out_size) {
    const float* x   = (const float*)d_in[0];
    const float* Wq  = (const float*)d_in[1];
    const float* bq  = (const float*)d_in[2];
    const float* Wk  = (const float*)d_in[3];
    const float* Wv  = (const float*)d_in[5];
    const float* bv  = (const float*)d_in[6];
    const float* Wfc = (const float*)d_in[7];
    const float* bfc = (const float*)d_in[8];
    float* out = (float*)d_out;

    float *pXR, *pAtt, *pAbar, *pOutBar, *pw2, *pv;
    __half *pXR16, *pY16, *pWkT16, *pWqT16, *pM3h, *pWv16, *pWfc16, *pZ16, *pObar16;
    cudaGetSymbolAddress((void**)&pXR, g_XR);
    cudaGetSymbolAddress((void**)&pAbar, g_Abar);
    cudaGetSymbolAddress((void**)&pOutBar, g_OutBar);
    cudaGetSymbolAddress((void**)&pw2, g_w2);
    cudaGetSymbolAddress((void**)&pv, g_vvec);
    cudaGetSymbolAddress((void**)&pXR16, g_XR16);
    cudaGetSymbolAddress((void**)&pY16, g_Y16);
    cudaGetSymbolAddress((void**)&pWkT16, g_WkT16);
    cudaGetSymbolAddress((void**)&pWqT16, g_WqT16);
    cudaGetSymbolAddress((void**)&pM3h, g_M3h);
    cudaGetSymbolAddress((void**)&pWv16, g_Wv16);
    cudaGetSymbolAddress((void**)&pWfc16, g_Wfc16);
    cudaGetSymbolAddress((void**)&pZ16, g_Z16);
    cudaGetSymbolAddress((void**)&pObar16, g_Obar16);

    if (out_size >= RES_ELEMS + ATT_ELEMS) pAtt = out + RES_ELEMS;
    else cudaGetSymbolAddress((void**)&pAtt, g_Att);

    cudaFuncSetAttribute(gemm_mma, cudaFuncAttributeMaxDynamicSharedMemorySize, DSM_BYTES);

    const float scale = rsqrtf((float)EE);
    const int nW = EE * EE;

    // 1) XR fp32 + fp16 split (single pass over x)
    build_xr_split<<<MROWS, 256>>>(x, pXR, pXR16);

    // 2) M3 = Wk^T Wq (fp16 2-term, K=4096) -> fp16 single
    dim3 gT(64, 64);
    split3t_f16<<<gT, 256>>>(Wk, pWkT16);
    split3t_f16<<<gT, 256>>>(Wq, pWqT16);
    dim3 gM3(EE / 128, EE / 128);
    gemm_mma<<<gM3, 256, DSM_BYTES>>>((const char*)pWkT16, (const char*)pWqT16,
        nullptr, pM3h, 64, 64, 32, 8192, 8192, 0, 0, 0, 0, 1.f, 2);

    // 3) Y = XRh @ M3h (fp16 1-term, K=2048) -> fp16 split
    dim3 gY(EE / 128, MROWS / 128);
    gemm_mma<<<gY, 256, DSM_BYTES>>>((const char*)pXR16, (const char*)pM3h,
        nullptr, pY16, 32, 32, 32, 8192, 4096, 0, 0, 0, 0, 1.f, 3);

    // 4) energy = scale * Y(2-term) @ XRh^T (batched over 32) -> fp32
    dim3 gE(512 / 128, 512 / 128, 32);
    gemm_mma<<<gE, 256, DSM_BYTES>>>((const char*)pY16, (const char*)pXR16,
        nullptr, pAtt, 64, 64, 32, 8192, 8192,
        512, (long long)512 * 8192, (long long)512 * 8192, (long long)512 * 512,
        scale, 0);

    // 5) bias column vector; softmax with +v[j]
    wkbq_kernel<<<EE / 256, 256>>>(Wk, bq, pw2);
    xrw2_kernel<<<MROWS / 8, 256>>>(pXR, pw2, pv, scale);
    softmax_rows<<<32 * 512, 128>>>(pAtt, pv);

    // 6) Abar, Z = Abar @ XR -> fp16 single
    abar_kernel<<<512, 512>>>(pAtt, pAbar);
    dim3 gZ(EE / 128, 32);
    zbar_f16<<<gZ, 128>>>(pAbar, pXR, pZ16);

    // 7) Obar = Z @ Wv^T + bv (fp16 1-term) -> fp16 single
    cast_f16<<<(nW + 255) / 256, 256>>>(Wv, pWv16, nW);
    dim3 gOb(EE / 128, 512 / 128);
    gemm_mma<<<gOb, 256, DSM_BYTES>>>((const char*)pZ16, (const char*)pWv16,
        bv, pObar16, 32, 32, 32, 4096, 4096, 0, 0, 0, 0, 1.f, 2);

    // 8) OutBar = Obar @ Wfc^T + bfc (fp16 1-term) -> fp32
    cast_f16<<<(nW + 255) / 256, 256>>>(Wfc, pWfc16, nW);
    gemm_mma<<<gOb, 256, DSM_BYTES>>>((const char*)pObar16, (const char*)pWfc16,
        bfc, pOutBar, 32, 32, 32, 4096, 4096, EE, 0, 0, 0, 1.f, 0);

    // 9) final output
    final_kernel<<<RES_ELEMS / 256, 256>>>(x, pOutBar, out);
}

// round 16
// speedup vs baseline: 2.6888x; 1.2964x over previous
#include <cuda_runtime.h>
#include <cuda_bf16.h>
#include <cuda_fp16.h>
#include <math.h>
#include <stdint.h>

// Problem dims
#define TT 16
#define BB 32
#define NN 512
#define FF 128
#define EE 2048            // F*T
#define MROWS 16384        // B*N
#define ATT_ELEMS (32*512*512)
#define RES_ELEMS (16*512*128)

// ---------------- device scratch ----------------
__device__ float g_XR[(size_t)MROWS * EE];
__device__ float g_Att[(size_t)ATT_ELEMS];
__device__ float g_Abar[(size_t)512 * 512];
__device__ float g_OutBar[(size_t)512 * EE];
__device__ float g_w2part[8 * EE];
__device__ float g_w2[EE];
__device__ float g_vvec[MROWS];

// fp16 buffers (all single-precision fp16, row ld = EE)
__device__ __half g_XR16[(size_t)MROWS * EE];
__device__ __half g_Y16 [(size_t)MROWS * EE];
__device__ __half g_WkT16[(size_t)EE * EE];
__device__ __half g_WqT16[(size_t)EE * EE];
__device__ __half g_M3h[(size_t)EE * EE];
__device__ __half g_Wv16 [(size_t)EE * EE];
__device__ __half g_Wfc16[(size_t)EE * EE];
__device__ __half g_Z16  [(size_t)512 * EE];
__device__ __half g_Obar16[(size_t)512 * EE];

// ================= helpers =================
__device__ __forceinline__ uint32_t smem_u32(const void* p) {
    uint32_t a;
    asm("{ .reg .u64 t; cvta.to.shared.u64 t, %1; cvt.u32.u64 %0, t; }" : "=r"(a) : "l"(p));
    return a;
}
#define SWZ128(off) ((off) ^ (((off) >> 3) & 0x70))

__device__ __forceinline__ void cp16(uint32_t s, const void* g) {
    asm volatile("cp.async.cg.shared.global [%0], [%1], 16;" :: "r"(s), "l"(g));
}
#define CP_COMMIT() asm volatile("cp.async.commit_group;" ::: "memory")
#define CP_WAIT1()  asm volatile("cp.async.wait_group 1;" ::: "memory")

__device__ __forceinline__ void ldmx4(uint32_t* f, uint32_t addr) {
    asm volatile("ldmatrix.sync.aligned.m8n8.x4.shared.b16 {%0,%1,%2,%3}, [%4];"
        : "=r"(f[0]), "=r"(f[1]), "=r"(f[2]), "=r"(f[3]) : "r"(addr));
}
__device__ __forceinline__ void mma16816(float* d, const uint32_t* a,
                                         uint32_t b0, uint32_t b1) {
    asm volatile("mma.sync.aligned.m16n8k16.row.col.f32.f16.f16.f32 "
        "{%0,%1,%2,%3}, {%4,%5,%6,%7}, {%8,%9}, {%0,%1,%2,%3};"
        : "+f"(d[0]), "+f"(d[1]), "+f"(d[2]), "+f"(d[3])
        : "r"(a[0]), "r"(a[1]), "r"(a[2]), "r"(a[3]), "r"(b0), "r"(b1));
}

#define STAGE_BYTES 32768      // A 16KB + B 16KB (128 rows x 128B per chunk)
#define DSM_BYTES (3 * STAGE_BYTES + 128)

// ================= fp16 mma.sync NT GEMM ========================================
// C = scale*(A[M,K] @ B[N,K]^T) + bias; fp16 operands, K = NCc*64 elems.
// Chunk c reads byte offset c*128 in each row (plain contiguous K).
// emit: 0 -> fp32 C (ld Ncols elems, batch stride sC elems); 2 -> fp16 (ld EE).
__global__ void __launch_bounds__(256, 2)
gemm_mma(const char* __restrict__ A, const char* __restrict__ B,
         const float* __restrict__ bias, void* __restrict__ Cv,
         int NCc, int ldA, int ldB,
         int Ncols, long long sAb, long long sBb, long long sC,
         float scale, int emit)
{
    extern __shared__ char sm[];
    A += (long long)blockIdx.z * sAb;
    B += (long long)blockIdx.z * sBb;

    const int tid = threadIdx.x, wid = tid >> 5, lane = tid & 31;
    const int row0 = blockIdx.y * 128, col0 = blockIdx.x * 128;
    const int wm = wid & 3, wn = wid >> 2;

    uint32_t sbase = (smem_u32(sm) + 127u) & ~127u;

    // loader: row = tid>>1, 4 x 16B chunks starting at (tid&1)*4
    const int lrow = tid >> 1;
    const int lc0 = (tid & 1) * 4;
    const char* gA = A + (long long)(row0 + lrow) * ldA;
    const char* gB = B + (long long)(col0 + lrow) * ldB;
    uint32_t swo[4];
#pragma unroll
    for (int q = 0; q < 4; q++) {
        uint32_t off = (uint32_t)lrow * 128u + (lc0 + q) * 16u;
        swo[q] = SWZ128(off);
    }

    // prologue: chunks 0,1 -> stages 0,1
#pragma unroll
    for (int s = 0; s < 2; s++) {
        uint32_t aA = sbase + s * STAGE_BYTES;
        uint32_t aB = aA + 16384;
        int kb = s * 128;
#pragma unroll
        for (int q = 0; q < 4; q++) {
            cp16(aA + swo[q], gA + kb + (lc0 + q) * 16);
            cp16(aB + swo[q], gB + kb + (lc0 + q) * 16);
        }
        CP_COMMIT();
    }

    float acc[2][8][4];
#pragma unroll
    for (int mi = 0; mi < 2; mi++)
#pragma unroll
        for (int ni = 0; ni < 8; ni++)
#pragma unroll
            for (int r = 0; r < 4; r++) acc[mi][ni][r] = 0.f;

    const int fr = lane & 15;
    const int fk = (lane >> 4) * 16;
    uint32_t arow[2], brow[4];
#pragma unroll
    for (int mi = 0; mi < 2; mi++) arow[mi] = (uint32_t)(wm * 32 + mi * 16 + fr) * 128u;
#pragma unroll
    for (int bi = 0; bi < 4; bi++) brow[bi] = (uint32_t)(wn * 64 + bi * 16 + fr) * 128u;

    int st_c = 0, st_n = 2;
    for (int c = 0; c < NCc; c++) {
        CP_WAIT1();               // chunk c resident
        __syncthreads();          // chunk c-1 consumed by all warps (stage st_n free)

        if (c + 2 < NCc) {
            uint32_t aA = sbase + st_n * STAGE_BYTES;
            uint32_t aB = aA + 16384;
            int kb = (c + 2) * 128;
#pragma unroll
            for (int q = 0; q < 4; q++) {
                cp16(aA + swo[q], gA + kb + (lc0 + q) * 16);
                cp16(aB + swo[q], gB + kb + (lc0 + q) * 16);
            }
        }
        CP_COMMIT();

        uint32_t aA = sbase + st_c * STAGE_BYTES;
        uint32_t aB = aA + 16384;

        uint32_t af[2][2][4];
        uint32_t bfA[2][4], bfB[2][4];

#pragma unroll
        for (int mi = 0; mi < 2; mi++)
            ldmx4(af[0][mi], aA + SWZ128(arow[mi] + fk));
#pragma unroll
        for (int p = 0; p < 2; p++)
            ldmx4(bfA[p], aB + SWZ128(brow[p] + fk));

#pragma unroll
        for (int ks = 0; ks < 4; ks++) {
            const int cur = ks & 1;
            const int kbyte = ks * 32 + fk;
            const int knext = kbyte + 32;

#pragma unroll
            for (int p = 0; p < 2; p++)
                ldmx4(bfB[p], aB + SWZ128(brow[2 + p] + kbyte));
            if (ks < 3) {
#pragma unroll
                for (int mi = 0; mi < 2; mi++)
                    ldmx4(af[cur ^ 1][mi], aA + SWZ128(arow[mi] + knext));
            }
#pragma unroll
            for (int p = 0; p < 2; p++)
#pragma unroll
                for (int mi = 0; mi < 2; mi++) {
                    mma16816(acc[mi][2 * p + 0], af[cur][mi], bfA[p][0], bfA[p][2]);
                    mma16816(acc[mi][2 * p + 1], af[cur][mi], bfA[p][1], bfA[p][3]);
                }
            if (ks < 3) {
#pragma unroll
                for (int p = 0; p < 2; p++)
                    ldmx4(bfA[p], aB + SWZ128(brow[p] + knext));
            }
#pragma unroll
            for (int p = 0; p < 2; p++)
#pragma unroll
                for (int mi = 0; mi < 2; mi++) {
                    mma16816(acc[mi][4 + 2 * p + 0], af[cur][mi], bfB[p][0], bfB[p][2]);
                    mma16816(acc[mi][4 + 2 * p + 1], af[cur][mi], bfB[p][1], bfB[p][3]);
                }
        }
        st_c = (st_c == 2) ? 0 : st_c + 1;
        st_n = (st_n == 2) ? 0 : st_n + 1;
    }

    // epilogue
#pragma unroll
    for (int mi = 0; mi < 2; mi++) {
        int r = row0 + wm * 32 + mi * 16 + (lane >> 2);
#pragma unroll
        for (int ni = 0; ni < 8; ni++) {
            int cc = col0 + wn * 64 + ni * 8 + (lane & 3) * 2;
            float b0 = bias ? bias[cc] : 0.f;
            float b1 = bias ? bias[cc + 1] : 0.f;
            float x0 = acc[mi][ni][0] * scale + b0;
            float y0 = acc[mi][ni][1] * scale + b1;
            float x1 = acc[mi][ni][2] * scale + b0;
            float y1 = acc[mi][ni][3] * scale + b1;
            if (emit == 0) {
                float* C = (float*)Cv + (long long)blockIdx.z * sC;
                float2 v0 = {x0, y0}, v1 = {x1, y1};
                *(float2*)(C + (long long)r * Ncols + cc) = v0;
                *(float2*)(C + (long long)(r + 8) * Ncols + cc) = v1;
            } else {
                __half* C = (__half*)Cv;
                __half2 h0, h1;
                h0.x = __float2half(x0); h0.y = __float2half(y0);
                h1.x = __float2half(x1); h1.y = __float2half(y1);
                *(__half2*)(C + (long long)r * EE + cc) = h0;
                *(__half2*)(C + (long long)(r + 8) * EE + cc) = h1;
            }
        }
    }
}

// ================= elementwise kernels =================
// fp32 -> fp16
__global__ void __launch_bounds__(256) cast_f16(const float* __restrict__ X,
                                                __half* __restrict__ Y, int n) {
    int i = blockIdx.x * 256 + threadIdx.x;
    if (i < n) Y[i] = __float2half(X[i]);
}

// transpose + fp16: Y16[r, k] = W[k, r]
__global__ void __launch_bounds__(256) castT_f16(const float* __restrict__ W,
                                                 __half* __restrict__ Y) {
    __shared__ float t[32][33];
    int tx = threadIdx.x & 31, ty = threadIdx.x >> 5;
    int cbase = blockIdx.x * 32;
    int rbase = blockIdx.y * 32;
#pragma unroll
    for (int j = 0; j < 4; j++)
        t[ty + j * 8][tx] = W[(size_t)(rbase + ty + j * 8) * EE + cbase + tx];
    __syncthreads();
#pragma unroll
    for (int j = 0; j < 4; j++) {
        int r = cbase + ty + j * 8;
        int k = rbase + tx;
        Y[(size_t)r * EE + k] = __float2half(t[tx][ty + j * 8]);
    }
}

// build XR fp32 + fp16 in one pass
__global__ void __launch_bounds__(256) build_xr_f16(const float* __restrict__ x,
                                                    float* __restrict__ xr,
                                                    __half* __restrict__ xr16) {
    __shared__ float s[TT * 129];
    int bn = blockIdx.x;
    int b = bn >> 9, n = bn & 511;
    for (int i = threadIdx.x; i < TT * FF; i += 256) {
        int t = i >> 7, f = i & 127;
        s[t * 129 + f] = x[((size_t)(t * BB + b) * NN + n) * FF + f];
    }
    __syncthreads();
    for (int e = threadIdx.x; e < EE; e += 256) {
        int t = e & 15, f = e >> 4;
        float v = s[t * 129 + f];
        xr[(size_t)bn * EE + e] = v;
        xr16[(size_t)bn * EE + e] = __float2half(v);
    }
}

// w2 = Wk^T bq, two-phase for parallelism
__global__ void __launch_bounds__(256) wkbq_part(const float* __restrict__ Wk,
                                                 const float* __restrict__ bq,
                                                 float* __restrict__ w2part) {
    int e = blockIdx.x * 256 + threadIdx.x;
    int d0 = blockIdx.y * 256;
    float s = 0.f;
#pragma unroll 4
    for (int d = d0; d < d0 + 256; d++) s += Wk[(size_t)d * EE + e] * bq[d];
    w2part[blockIdx.y * EE + e] = s;
}
__global__ void __launch_bounds__(256) wkbq_reduce(const float* __restrict__ w2part,
                                                   float* __restrict__ w2) {
    int e = blockIdx.x * 256 + threadIdx.x;
    float s = 0.f;
#pragma unroll
    for (int p = 0; p < 8; p++) s += w2part[p * EE + e];
    w2[e] = s;
}
__global__ void __launch_bounds__(256) xrw2_kernel(const float* __restrict__ XR,
                                                   const float* __restrict__ w2,
                                                   float* __restrict__ v, float scale) {
    int g = blockIdx.x * 8 + (threadIdx.x >> 5);
    int lane = threadIdx.x & 31;
    const float* r = XR + (size_t)g * EE;
    float s = 0.f;
    for (int e = lane; e < EE; e += 32) s += r[e] * w2[e];
#pragma unroll
    for (int o = 16; o; o >>= 1) s += __shfl_xor_sync(0xffffffffu, s, o);
    if (lane == 0) v[g] = s * scale;
}

__global__ void __launch_bounds__(128) softmax_rows(float* __restrict__ att,
                                                    const float* __restrict__ vadd) {
    size_t row = blockIdx.x;
    int b = (int)(row >> 9);
    float4* p = (float4*)(att + row * 512);
    const float4* vv = (const float4*)(vadd + (size_t)b * 512);
    float4 v = p[threadIdx.x];
    float4 a = vv[threadIdx.x];
    v.x += a.x; v.y += a.y; v.z += a.z; v.w += a.w;
    float m = fmaxf(fmaxf(v.x, v.y), fmaxf(v.z, v.w));
#pragma unroll
    for (int o = 16; o; o >>= 1) m = fmaxf(m, __shfl_xor_sync(0xffffffffu, m, o));
    __shared__ float sm[4];
    if ((threadIdx.x & 31) == 0) sm[threadIdx.x >> 5] = m;
    __syncthreads();
    m = fmaxf(fmaxf(sm[0], sm[1]), fmaxf(sm[2], sm[3]));
    v.x = __expf(v.x - m); v.y = __expf(v.y - m);
    v.z = __expf(v.z - m); v.w = __expf(v.w - m);
    float s = v.x + v.y + v.z + v.w;
#pragma unroll
    for (int o = 16; o; o >>= 1) s += __shfl_xor_sync(0xffffffffu, s, o);
    __shared__ float ss[4];
    if ((threadIdx.x & 31) == 0) ss[threadIdx.x >> 5] = s;
    __syncthreads();
    s = ss[0] + ss[1] + ss[2] + ss[3];
    float inv = 1.f / s;
    v.x *= inv; v.y *= inv; v.z *= inv; v.w *= inv;
    p[threadIdx.x] = v;
}

__global__ void __launch_bounds__(512) abar_kernel(const float* __restrict__ att,
                                                   float* __restrict__ abar) {
    int bg = blockIdx.x;
    int b = bg >> 4, g = bg & 15;
    const float* bse = att + ((size_t)b * 512 + g * 32) * 512;
    int j = threadIdx.x;
    float s = 0.f;
#pragma unroll 8
    for (int r = 0; r < 32; r++) s += bse[(size_t)r * 512 + j];
    abar[(size_t)bg * 512 + j] = s * (1.f / 32.f);
}

// Z = Abar_b @ XR_b -> fp16
__global__ void __launch_bounds__(128) zbar_f16(const float* __restrict__ abar,
                                                const float* __restrict__ XR,
                                                __half* __restrict__ Z16) {
    int b = blockIdx.y;
    int col0 = blockIdx.x * 128;
    __shared__ float sA[16 * 512];
    for (int i = threadIdx.x; i < 16 * 512; i += 128)
        sA[i] = abar[(size_t)b * 16 * 512 + i];
    __syncthreads();
    float acc[16];
#pragma unroll
    for (int g = 0; g < 16; g++) acc[g] = 0.f;
    const float* vb = XR + (size_t)b * 512 * EE + col0 + threadIdx.x;
    for (int l = 0; l < 512; l++) {
        float vv = vb[(size_t)l * EE];
#pragma unroll
        for (int g = 0; g < 16; g++) acc[g] = fmaf(sA[g * 512 + l], vv, acc[g]);
    }
#pragma unroll
    for (int g = 0; g < 16; g++)
        Z16[((size_t)b * 16 + g) * EE + col0 + threadIdx.x] = __float2half(acc[g]);
}

__global__ void __launch_bounds__(256) final_kernel(const float* __restrict__ x,
                                                    const float* __restrict__ outbar,
                                                    float* __restrict__ out) {
    int idx = blockIdx.x * 256 + threadIdx.x;
    int f = idx & 127;
    int i = (idx >> 7) & 511;
    int t = idx >> 16;
    const float* px = x + (size_t)t * (BB * NN * FF) + (size_t)i * FF + f;
    float s = 0.f;
#pragma unroll 8
    for (int b = 0; b < 32; b++) s += px[(size_t)b * (NN * FF)];
    out[idx] = s * (1.f / 32.f) + outbar[(size_t)i * EE + t * FF + f];
}

// ---------------- launcher ----------------
extern "C" void kernel_launch(void* const* d_in, const int* in_sizes, int n_in,
                              void* d_out, int out_size) {
    const float* x   = (const float*)d_in[0];
    const float* Wq  = (const float*)d_in[1];
    const float* bq  = (const float*)d_in[2];
    const float* Wk  = (const float*)d_in[3];
    const float* Wv  = (const float*)d_in[5];
    const float* bv  = (const float*)d_in[6];
    const float* Wfc = (const float*)d_in[7];
    const float* bfc = (const float*)d_in[8];
    float* out = (float*)d_out;

    float *pXR, *pAtt, *pAbar, *pOutBar, *pw2p, *pw2, *pv;
    __half *pXR16, *pY16, *pWkT16, *pWqT16, *pM3h, *pWv16, *pWfc16, *pZ16, *pObar16;
    cudaGetSymbolAddress((void**)&pXR, g_XR);
    cudaGetSymbolAddress((void**)&pAbar, g_Abar);
    cudaGetSymbolAddress((void**)&pOutBar, g_OutBar);
    cudaGetSymbolAddress((void**)&pw2p, g_w2part);
    cudaGetSymbolAddress((void**)&pw2, g_w2);
    cudaGetSymbolAddress((void**)&pv, g_vvec);
    cudaGetSymbolAddress((void**)&pXR16, g_XR16);
    cudaGetSymbolAddress((void**)&pY16, g_Y16);
    cudaGetSymbolAddress((void**)&pWkT16, g_WkT16);
    cudaGetSymbolAddress((void**)&pWqT16, g_WqT16);
    cudaGetSymbolAddress((void**)&pM3h, g_M3h);
    cudaGetSymbolAddress((void**)&pWv16, g_Wv16);
    cudaGetSymbolAddress((void**)&pWfc16, g_Wfc16);
    cudaGetSymbolAddress((void**)&pZ16, g_Z16);
    cudaGetSymbolAddress((void**)&pObar16, g_Obar16);

    if (out_size >= RES_ELEMS + ATT_ELEMS) pAtt = out + RES_ELEMS;
    else cudaGetSymbolAddress((void**)&pAtt, g_Att);

    cudaFuncSetAttribute(gemm_mma, cudaFuncAttributeMaxDynamicSharedMemorySize, DSM_BYTES);

    const float scale = rsqrtf((float)EE);
    const int nW = EE * EE;

    // 1) XR fp32 + fp16 (single pass over x)
    build_xr_f16<<<MROWS, 256>>>(x, pXR, pXR16);

    // 2) M3 = Wk^T Wq (fp16 1-term, K=2048) -> fp16
    dim3 gT(64, 64);
    castT_f16<<<gT, 256>>>(Wk, pWkT16);
    castT_f16<<<gT, 256>>>(Wq, pWqT16);
    dim3 gM3(EE / 128, EE / 128);
    gemm_mma<<<gM3, 256, DSM_BYTES>>>((const char*)pWkT16, (const char*)pWqT16,
        nullptr, pM3h, 32, 4096, 4096, 0, 0, 0, 0, 1.f, 2);

    // 3) Y = XRh @ M3h (fp16 1-term) -> fp16
    dim3 gY(EE / 128, MROWS / 128);
    gemm_mma<<<gY, 256, DSM_BYTES>>>((const char*)pXR16, (const char*)pM3h,
        nullptr, pY16, 32, 4096, 4096, 0, 0, 0, 0, 1.f, 2);

    // 4) energy = scale * Yh @ XRh^T (fp16 1-term, batched over 32) -> fp32
    dim3 gE(512 / 128, 512 / 128, 32);
    gemm_mma<<<gE, 256, DSM_BYTES>>>((const char*)pY16, (const char*)pXR16,
        nullptr, pAtt, 32, 4096, 4096,
        512, (long long)512 * 4096, (long long)512 * 4096, (long long)512 * 512,
        scale, 0);

    // 5) bias column vector; softmax with +v[j]
    dim3 gW(8, 8);
    wkbq_part<<<gW, 256>>>(Wk, bq, pw2p);
    wkbq_reduce<<<8, 256>>>(pw2p, pw2);
    xrw2_kernel<<<MROWS / 8, 256>>>(pXR, pw2, pv, scale);
    softmax_rows<<<32 * 512, 128>>>(pAtt, pv);

    // 6) Abar, Z = Abar @ XR -> fp16
    abar_kernel<<<512, 512>>>(pAtt, pAbar);
    dim3 gZ(EE / 128, 32);
    zbar_f16<<<gZ, 128>>>(pAbar, pXR, pZ16);

    // 7) Obar = Z @ Wv^T + bv (fp16 1-term) -> fp16
    cast_f16<<<(nW + 255) / 256, 256>>>(Wv, pWv16, nW);
    dim3 gOb(EE / 128, 512 / 128);
    gemm_mma<<<gOb, 256, DSM_BYTES>>>((const char*)pZ16, (const char*)pWv16,
        bv, pObar16, 32, 4096, 4096, 0, 0, 0, 0, 1.f, 2);

    // 8) OutBar = Obar @ Wfc^T + bfc (fp16 1-term) -> fp32
    cast_f16<<<(nW + 255) / 256, 256>>>(Wfc, pWfc16, nW);
    gemm_mma<<<gOb, 256, DSM_BYTES>>>((const char*)pObar16, (const char*)pWfc16,
        bfc, pOutBar, 32, 4096, 4096, EE, 0, 0, 0, 1.f, 0);

    // 9) final output
    final_kernel<<<RES_ELEMS / 256, 256>>>(x, pOutBar, out);
}

// round 17
// speedup vs baseline: 2.7965x; 1.0401x over previous
#include <cuda_runtime.h>
#include <cuda_bf16.h>
#include <cuda_fp16.h>
#include <math.h>
#include <stdint.h>

// Problem dims
#define TT 16
#define BB 32
#define NN 512
#define FF 128
#define EE 2048            // F*T
#define MROWS 16384        // B*N
#define ATT_ELEMS (32*512*512)
#define RES_ELEMS (16*512*128)

// ---------------- device scratch ----------------
__device__ float g_Att[(size_t)ATT_ELEMS];
__device__ float g_Abar[(size_t)512 * 512];
__device__ float g_OutBar[(size_t)512 * EE];
__device__ float g_Xmean[(size_t)RES_ELEMS];
__device__ float g_w2part[8 * EE];
__device__ float g_w2[EE];
__device__ float g_vvec[MROWS];

// fp16 buffers (row ld = EE)
__device__ __half g_XR16[(size_t)MROWS * EE];
__device__ __half g_Y16 [(size_t)MROWS * EE];
__device__ __half g_WkT16[(size_t)EE * EE];
__device__ __half g_WqT16[(size_t)EE * EE];
__device__ __half g_M3h[(size_t)EE * EE];
__device__ __half g_Wv16 [(size_t)EE * EE];
__device__ __half g_Wfc16[(size_t)EE * EE];
__device__ __half g_Z16  [(size_t)512 * EE];
__device__ __half g_Obar16[(size_t)512 * EE];

// ================= helpers =================
__device__ __forceinline__ uint32_t smem_u32(const void* p) {
    uint32_t a;
    asm("{ .reg .u64 t; cvta.to.shared.u64 t, %1; cvt.u32.u64 %0, t; }" : "=r"(a) : "l"(p));
    return a;
}
#define SWZ128(off) ((off) ^ (((off) >> 3) & 0x70))

__device__ __forceinline__ void cp16(uint32_t s, const void* g) {
    asm volatile("cp.async.cg.shared.global [%0], [%1], 16;" :: "r"(s), "l"(g));
}
#define CP_COMMIT() asm volatile("cp.async.commit_group;" ::: "memory")
#define CP_WAIT1()  asm volatile("cp.async.wait_group 1;" ::: "memory")

__device__ __forceinline__ void ldmx4(uint32_t* f, uint32_t addr) {
    asm volatile("ldmatrix.sync.aligned.m8n8.x4.shared.b16 {%0,%1,%2,%3}, [%4];"
        : "=r"(f[0]), "=r"(f[1]), "=r"(f[2]), "=r"(f[3]) : "r"(addr));
}
__device__ __forceinline__ void mma16816(float* d, const uint32_t* a,
                                         uint32_t b0, uint32_t b1) {
    asm volatile("mma.sync.aligned.m16n8k16.row.col.f32.f16.f16.f32 "
        "{%0,%1,%2,%3}, {%4,%5,%6,%7}, {%8,%9}, {%0,%1,%2,%3};"
        : "+f"(d[0]), "+f"(d[1]), "+f"(d[2]), "+f"(d[3])
        : "r"(a[0]), "r"(a[1]), "r"(a[2]), "r"(a[3]), "r"(b0), "r"(b1));
}

#define STAGE_BYTES 32768      // A 16KB + B 16KB (128 rows x 128B per chunk)
#define DSM_BYTES (3 * STAGE_BYTES + 128)

// ================= fp16 mma.sync NT GEMM ========================================
// C = scale*(A[M,K] @ B[N,K]^T) + bias; fp16 operands, K = NCc*64 elems.
// emit: 0 -> fp32 C (ld Ncols elems, batch stride sC elems); 2 -> fp16 (ld EE).
__global__ void __launch_bounds__(256, 2)
gemm_mma(const char* __restrict__ A, const char* __restrict__ B,
         const float* __restrict__ bias, void* __restrict__ Cv,
         int NCc, int ldA, int ldB,
         int Ncols, long long sAb, long long sBb, long long sC,
         float scale, int emit)
{
    extern __shared__ char sm[];
    A += (long long)blockIdx.z * sAb;
    B += (long long)blockIdx.z * sBb;

    const int tid = threadIdx.x, wid = tid >> 5, lane = tid & 31;
    const int row0 = blockIdx.y * 128, col0 = blockIdx.x * 128;
    const int wm = wid & 3, wn = wid >> 2;

    uint32_t sbase = (smem_u32(sm) + 127u) & ~127u;

    const int lrow = tid >> 1;
    const int lc0 = (tid & 1) * 4;
    const char* gA = A + (long long)(row0 + lrow) * ldA;
    const char* gB = B + (long long)(col0 + lrow) * ldB;
    uint32_t swo[4];
#pragma unroll
    for (int q = 0; q < 4; q++) {
        uint32_t off = (uint32_t)lrow * 128u + (lc0 + q) * 16u;
        swo[q] = SWZ128(off);
    }

#pragma unroll
    for (int s = 0; s < 2; s++) {
        uint32_t aA = sbase + s * STAGE_BYTES;
        uint32_t aB = aA + 16384;
        int kb = s * 128;
#pragma unroll
        for (int q = 0; q < 4; q++) {
            cp16(aA + swo[q], gA + kb + (lc0 + q) * 16);
            cp16(aB + swo[q], gB + kb + (lc0 + q) * 16);
        }
        CP_COMMIT();
    }

    float acc[2][8][4];
#pragma unroll
    for (int mi = 0; mi < 2; mi++)
#pragma unroll
        for (int ni = 0; ni < 8; ni++)
#pragma unroll
            for (int r = 0; r < 4; r++) acc[mi][ni][r] = 0.f;

    const int fr = lane & 15;
    const int fk = (lane >> 4) * 16;
    uint32_t arow[2], brow[4];
#pragma unroll
    for (int mi = 0; mi < 2; mi++) arow[mi] = (uint32_t)(wm * 32 + mi * 16 + fr) * 128u;
#pragma unroll
    for (int bi = 0; bi < 4; bi++) brow[bi] = (uint32_t)(wn * 64 + bi * 16 + fr) * 128u;

    int st_c = 0, st_n = 2;
    for (int c = 0; c < NCc; c++) {
        CP_WAIT1();
        __syncthreads();

        if (c + 2 < NCc) {
            uint32_t aA = sbase + st_n * STAGE_BYTES;
            uint32_t aB = aA + 16384;
            int kb = (c + 2) * 128;
#pragma unroll
            for (int q = 0; q < 4; q++) {
                cp16(aA + swo[q], gA + kb + (lc0 + q) * 16);
                cp16(aB + swo[q], gB + kb + (lc0 + q) * 16);
            }
        }
        CP_COMMIT();

        uint32_t aA = sbase + st_c * STAGE_BYTES;
        uint32_t aB = aA + 16384;

        uint32_t af[2][2][4];
        uint32_t bfA[2][4], bfB[2][4];

#pragma unroll
        for (int mi = 0; mi < 2; mi++)
            ldmx4(af[0][mi], aA + SWZ128(arow[mi] + fk));
#pragma unroll
        for (int p = 0; p < 2; p++)
            ldmx4(bfA[p], aB + SWZ128(brow[p] + fk));

#pragma unroll
        for (int ks = 0; ks < 4; ks++) {
            const int cur = ks & 1;
            const int kbyte = ks * 32 + fk;
            const int knext = kbyte + 32;

#pragma unroll
            for (int p = 0; p < 2; p++)
                ldmx4(bfB[p], aB + SWZ128(brow[2 + p] + kbyte));
            if (ks < 3) {
#pragma unroll
                for (int mi = 0; mi < 2; mi++)
                    ldmx4(af[cur ^ 1][mi], aA + SWZ128(arow[mi] + knext));
            }
#pragma unroll
            for (int p = 0; p < 2; p++)
#pragma unroll
                for (int mi = 0; mi < 2; mi++) {
                    mma16816(acc[mi][2 * p + 0], af[cur][mi], bfA[p][0], bfA[p][2]);
                    mma16816(acc[mi][2 * p + 1], af[cur][mi], bfA[p][1], bfA[p][3]);
                }
            if (ks < 3) {
#pragma unroll
                for (int p = 0; p < 2; p++)
                    ldmx4(bfA[p], aB + SWZ128(brow[p] + knext));
            }
#pragma unroll
            for (int p = 0; p < 2; p++)
#pragma unroll
                for (int mi = 0; mi < 2; mi++) {
                    mma16816(acc[mi][4 + 2 * p + 0], af[cur][mi], bfB[p][0], bfB[p][2]);
                    mma16816(acc[mi][4 + 2 * p + 1], af[cur][mi], bfB[p][1], bfB[p][3]);
                }
        }
        st_c = (st_c == 2) ? 0 : st_c + 1;
        st_n = (st_n == 2) ? 0 : st_n + 1;
    }

    // epilogue
#pragma unroll
    for (int mi = 0; mi < 2; mi++) {
        int r = row0 + wm * 32 + mi * 16 + (lane >> 2);
#pragma unroll
        for (int ni = 0; ni < 8; ni++) {
            int cc = col0 + wn * 64 + ni * 8 + (lane & 3) * 2;
            float b0 = bias ? bias[cc] : 0.f;
            float b1 = bias ? bias[cc + 1] : 0.f;
            float x0 = acc[mi][ni][0] * scale + b0;
            float y0 = acc[mi][ni][1] * scale + b1;
            float x1 = acc[mi][ni][2] * scale + b0;
            float y1 = acc[mi][ni][3] * scale + b1;
            if (emit == 0) {
                float* C = (float*)Cv + (long long)blockIdx.z * sC;
                float2 v0 = {x0, y0}, v1 = {x1, y1};
                *(float2*)(C + (long long)r * Ncols + cc) = v0;
                *(float2*)(C + (long long)(r + 8) * Ncols + cc) = v1;
            } else {
                __half* C = (__half*)Cv;
                __half2 h0, h1;
                h0.x = __float2half(x0); h0.y = __float2half(y0);
                h1.x = __float2half(x1); h1.y = __float2half(y1);
                *(__half2*)(C + (long long)r * EE + cc) = h0;
                *(__half2*)(C + (long long)(r + 8) * EE + cc) = h1;
            }
        }
    }
}

// ================= elementwise kernels =================
// fp32 -> fp16, two matrices selected by blockIdx.y
__global__ void __launch_bounds__(256) cast2_f16(const float* __restrict__ X0,
                                                 const float* __restrict__ X1,
                                                 __half* __restrict__ Y0,
                                                 __half* __restrict__ Y1, int n) {
    int i = blockIdx.x * 256 + threadIdx.x;
    if (i >= n) return;
    if (blockIdx.y == 0) Y0[i] = __float2half(X0[i]);
    else                 Y1[i] = __float2half(X1[i]);
}

// transpose + fp16 for two matrices (blockIdx.z selects)
__global__ void __launch_bounds__(256) castT2_f16(const float* __restrict__ W0,
                                                  const float* __restrict__ W1,
                                                  __half* __restrict__ Y0,
                                                  __half* __restrict__ Y1) {
    __shared__ float t[32][33];
    const float* W = blockIdx.z ? W1 : W0;
    __half* Y = blockIdx.z ? Y1 : Y0;
    int tx = threadIdx.x & 31, ty = threadIdx.x >> 5;
    int cbase = blockIdx.x * 32;
    int rbase = blockIdx.y * 32;
#pragma unroll
    for (int j = 0; j < 4; j++)
        t[ty + j * 8][tx] = W[(size_t)(rbase + ty + j * 8) * EE + cbase + tx];
    __syncthreads();
#pragma unroll
    for (int j = 0; j < 4; j++) {
        int r = cbase + ty + j * 8;
        int k = rbase + tx;
        Y[(size_t)r * EE + k] = __float2half(t[tx][ty + j * 8]);
    }
}

// build XR16 + x_mean in one pass: one block per node n, loop over b
__global__ void __launch_bounds__(256) build_xr_mean(const float* __restrict__ x,
                                                     __half* __restrict__ xr16,
                                                     float* __restrict__ xmean) {
    __shared__ float s[TT * 129];
    int n = blockIdx.x;
    float accr[8];
#pragma unroll
    for (int j = 0; j < 8; j++) accr[j] = 0.f;

    for (int b = 0; b < BB; b++) {
#pragma unroll
        for (int j = 0; j < 8; j++) {
            int i = threadIdx.x + j * 256;
            int t = i >> 7, f = i & 127;
            float v = x[((size_t)(t * BB + b) * NN + n) * FF + f];
            s[t * 129 + f] = v;
            accr[j] += v;
        }
        __syncthreads();
        size_t rb = (size_t)(b * NN + n) * EE;
#pragma unroll
        for (int j = 0; j < 8; j++) {
            int e = threadIdx.x + j * 256;
            int t = e & 15, f = e >> 4;
            xr16[rb + e] = __float2half(s[t * 129 + f]);
        }
        __syncthreads();
    }
#pragma unroll
    for (int j = 0; j < 8; j++) {
        int i = threadIdx.x + j * 256;
        int t = i >> 7, f = i & 127;
        xmean[((size_t)t * NN + n) * FF + f] = accr[j] * (1.f / 32.f);
    }
}

// w2 = Wk^T bq, two-phase
__global__ void __launch_bounds__(256) wkbq_part(const float* __restrict__ Wk,
                                                 const float* __restrict__ bq,
                                                 float* __restrict__ w2part) {
    int e = blockIdx.x * 256 + threadIdx.x;
    int d0 = blockIdx.y * 256;
    float s = 0.f;
#pragma unroll 4
    for (int d = d0; d < d0 + 256; d++) s += Wk[(size_t)d * EE + e] * bq[d];
    w2part[blockIdx.y * EE + e] = s;
}
__global__ void __launch_bounds__(256) wkbq_reduce(const float* __restrict__ w2part,
                                                   float* __restrict__ w2) {
    int e = blockIdx.x * 256 + threadIdx.x;
    float s = 0.f;
#pragma unroll
    for (int p = 0; p < 8; p++) s += w2part[p * EE + e];
    w2[e] = s;
}
// v = scale * XR16 @ w2
__global__ void __launch_bounds__(256) xrw2_kernel(const __half* __restrict__ XR16,
                                                   const float* __restrict__ w2,
                                                   float* __restrict__ v, float scale) {
    int g = blockIdx.x * 8 + (threadIdx.x >> 5);
    int lane = threadIdx.x & 31;
    const __half* r = XR16 + (size_t)g * EE;
    float s = 0.f;
    for (int e = lane; e < EE; e += 32) s += __half2float(r[e]) * w2[e];
#pragma unroll
    for (int o = 16; o; o >>= 1) s += __shfl_xor_sync(0xffffffffu, s, o);
    if (lane == 0) v[g] = s * scale;
}

// fused softmax (+v) and group-mean: one block per (b,g) group of 32 rows
__global__ void __launch_bounds__(256) softmax_abar(float* __restrict__ att,
                                                    const float* __restrict__ vadd,
                                                    float* __restrict__ abar) {
    extern __shared__ float tile[];     // 32 x 512 floats = 64KB
    int bg = blockIdx.x;
    int b = bg >> 4;
    float* base = att + (size_t)bg * 32 * 512;
    const float* vv = vadd + (size_t)b * 512;
    int tid = threadIdx.x;

    for (int i = tid; i < 32 * 512; i += 256)
        tile[i] = base[i] + vv[i & 511];
    __syncthreads();

    int wid = tid >> 5, lane = tid & 31;
    for (int r = wid; r < 32; r += 8) {
        float* row = tile + r * 512;
        float vals[16];
        float m = -1e30f;
#pragma unroll
        for (int q = 0; q < 4; q++) {
            float4 v4 = ((float4*)row)[lane + q * 32];
            vals[q * 4 + 0] = v4.x; vals[q * 4 + 1] = v4.y;
            vals[q * 4 + 2] = v4.z; vals[q * 4 + 3] = v4.w;
            m = fmaxf(m, fmaxf(fmaxf(v4.x, v4.y), fmaxf(v4.z, v4.w)));
        }
#pragma unroll
        for (int o = 16; o; o >>= 1) m = fmaxf(m, __shfl_xor_sync(0xffffffffu, m, o));
        float s = 0.f;
#pragma unroll
        for (int k = 0; k < 16; k++) { vals[k] = __expf(vals[k] - m); s += vals[k]; }
#pragma unroll
        for (int o = 16; o; o >>= 1) s += __shfl_xor_sync(0xffffffffu, s, o);
        float inv = 1.f / s;
#pragma unroll
        for (int q = 0; q < 4; q++) {
            float4 v4;
            v4.x = vals[q * 4 + 0] * inv; v4.y = vals[q * 4 + 1] * inv;
            v4.z = vals[q * 4 + 2] * inv; v4.w = vals[q * 4 + 3] * inv;
            ((float4*)row)[lane + q * 32] = v4;
        }
    }
    __syncthreads();

    for (int i = tid; i < 32 * 512; i += 256) base[i] = tile[i];
    for (int c = tid; c < 512; c += 256) {
        float s = 0.f;
#pragma unroll 8
        for (int r = 0; r < 32; r++) s += tile[r * 512 + c];
        abar[(size_t)bg * 512 + c] = s * (1.f / 32.f);
    }
}

// Z = Abar_b @ XR16_b -> fp16
__global__ void __launch_bounds__(128) zbar_f16(const float* __restrict__ abar,
                                                const __half* __restrict__ XR16,
                                                __half* __restrict__ Z16) {
    int b = blockIdx.y;
    int col0 = blockIdx.x * 128;
    __shared__ float sA[16 * 512];
    for (int i = threadIdx.x; i < 16 * 512; i += 128)
        sA[i] = abar[(size_t)b * 16 * 512 + i];
    __syncthreads();
    float acc[16];
#pragma unroll
    for (int g = 0; g < 16; g++) acc[g] = 0.f;
    const __half* vb = XR16 + (size_t)b * 512 * EE + col0 + threadIdx.x;
    for (int l = 0; l < 512; l++) {
        float vv = __half2float(vb[(size_t)l * EE]);
#pragma unroll
        for (int g = 0; g < 16; g++) acc[g] = fmaf(sA[g * 512 + l], vv, acc[g]);
    }
#pragma unroll
    for (int g = 0; g < 16; g++)
        Z16[((size_t)b * 16 + g) * EE + col0 + threadIdx.x] = __float2half(acc[g]);
}

__global__ void __launch_bounds__(256) final_kernel(const float* __restrict__ xmean,
                                                    const float* __restrict__ outbar,
                                                    float* __restrict__ out) {
    int idx = blockIdx.x * 256 + threadIdx.x;
    int f = idx & 127;
    int i = (idx >> 7) & 511;
    int t = idx >> 16;
    out[idx] = xmean[idx] + outbar[(size_t)i * EE + t * FF + f];
}

// ---------------- launcher ----------------
extern "C" void kernel_launch(void* const* d_in, const int* in_sizes, int n_in,
                              void* d_out, int out_size) {
    const float* x   = (const float*)d_in[0];
    const float* Wq  = (const float*)d_in[1];
    const float* bq  = (const float*)d_in[2];
    const float* Wk  = (const float*)d_in[3];
    const float* Wv  = (const float*)d_in[5];
    const float* bv  = (const float*)d_in[6];
    const float* Wfc = (const float*)d_in[7];
    const float* bfc = (const float*)d_in[8];
    float* out = (float*)d_out;

    float *pAtt, *pAbar, *pOutBar, *pXmean, *pw2p, *pw2, *pv;
    __half *pXR16, *pY16, *pWkT16, *pWqT16, *pM3h, *pWv16, *pWfc16, *pZ16, *pObar16;
    cudaGetSymbolAddress((void**)&pAbar, g_Abar);
    cudaGetSymbolAddress((void**)&pOutBar, g_OutBar);
    cudaGetSymbolAddress((void**)&pXmean, g_Xmean);
    cudaGetSymbolAddress((void**)&pw2p, g_w2part);
    cudaGetSymbolAddress((void**)&pw2, g_w2);
    cudaGetSymbolAddress((void**)&pv, g_vvec);
    cudaGetSymbolAddress((void**)&pXR16, g_XR16);
    cudaGetSymbolAddress((void**)&pY16, g_Y16);
    cudaGetSymbolAddress((void**)&pWkT16, g_WkT16);
    cudaGetSymbolAddress((void**)&pWqT16, g_WqT16);
    cudaGetSymbolAddress((void**)&pM3h, g_M3h);
    cudaGetSymbolAddress((void**)&pWv16, g_Wv16);
    cudaGetSymbolAddress((void**)&pWfc16, g_Wfc16);
    cudaGetSymbolAddress((void**)&pZ16, g_Z16);
    cudaGetSymbolAddress((void**)&pObar16, g_Obar16);

    if (out_size >= RES_ELEMS + ATT_ELEMS) pAtt = out + RES_ELEMS;
    else cudaGetSymbolAddress((void**)&pAtt, g_Att);

    cudaFuncSetAttribute(gemm_mma, cudaFuncAttributeMaxDynamicSharedMemorySize, DSM_BYTES);
    cudaFuncSetAttribute(softmax_abar, cudaFuncAttributeMaxDynamicSharedMemorySize, 65536);

    const float scale = rsqrtf((float)EE);
    const int nW = EE * EE;

    // 1) XR16 + x_mean (single pass over x)
    build_xr_mean<<<NN, 256>>>(x, pXR16, pXmean);

    // 2) M3 = Wk^T Wq (fp16 1-term) -> fp16
    dim3 gT(64, 64, 2);
    castT2_f16<<<gT, 256>>>(Wk, Wq, pWkT16, pWqT16);
    dim3 gM3(EE / 128, EE / 128);
    gemm_mma<<<gM3, 256, DSM_BYTES>>>((const char*)pWkT16, (const char*)pWqT16,
        nullptr, pM3h, 32, 4096, 4096, 0, 0, 0, 0, 1.f, 2);

    // 3) Y = XRh @ M3h (fp16 1-term) -> fp16
    dim3 gY(EE / 128, MROWS / 128);
    gemm_mma<<<gY, 256, DSM_BYTES>>>((const char*)pXR16, (const char*)pM3h,
        nullptr, pY16, 32, 4096, 4096, 0, 0, 0, 0, 1.f, 2);

    // 4) energy = scale * Yh @ XRh^T (batched over 32) -> fp32
    dim3 gE(512 / 128, 512 / 128, 32);
    gemm_mma<<<gE, 256, DSM_BYTES>>>((const char*)pY16, (const char*)pXR16,
        nullptr, pAtt, 32, 4096, 4096,
        512, (long long)512 * 4096, (long long)512 * 4096, (long long)512 * 512,
        scale, 0);

    // 5) bias column vector; fused softmax(+v) + group-mean
    dim3 gW(8, 8);
    wkbq_part<<<gW, 256>>>(Wk, bq, pw2p);
    wkbq_reduce<<<8, 256>>>(pw2p, pw2);
    xrw2_kernel<<<MROWS / 8, 256>>>(pXR16, pw2, pv, scale);
    softmax_abar<<<512, 256, 65536>>>(pAtt, pv, pAbar);

    // 6) Z = Abar @ XR16 -> fp16
    dim3 gZ(EE / 128, 32);
    zbar_f16<<<gZ, 128>>>(pAbar, pXR16, pZ16);

    // 7) Obar = Z @ Wv^T + bv (fp16 1-term) -> fp16
    dim3 gC((nW + 255) / 256, 2);
    cast2_f16<<<gC, 256>>>(Wv, Wfc, pWv16, pWfc16, nW);
    dim3 gOb(EE / 128, 512 / 128);
    gemm_mma<<<gOb, 256, DSM_BYTES>>>((const char*)pZ16, (const char*)pWv16,
        bv, pObar16, 32, 4096, 4096, 0, 0, 0, 0, 1.f, 2);

    // 8) OutBar = Obar @ Wfc^T + bfc (fp16 1-term) -> fp32
    gemm_mma<<<gOb, 256, DSM_BYTES>>>((const char*)pObar16, (const char*)pWfc16,
        bfc, pOutBar, 32, 4096, 4096, EE, 0, 0, 0, 1.f, 0);

    // 9) final output
    final_kernel<<<RES_ELEMS / 256, 256>>>(pXmean, pOutBar, out);
}